// round 1
// baseline (speedup 1.0000x reference)
#include <cuda_runtime.h>

// ---------------- problem constants ----------------
#define M_TOT   141512      // 2888 windows * 49 tokens
#define NB      2888        // 8 * 19 * 19
#define QHW     19          // windows per side (ceil(133/7))
#define LWIN    49
#define CDIM    512
#define NHEADS  16
#define HDIM    32

// ---------------- scratch (static device allocations) ----------------
__device__ __align__(16) float g_qkv[217362432];  // M_TOT * 1536
__device__ __align__(16) float g_att[72454144];   // M_TOT * 512

// Map a flattened window-token row m -> offset (in floats) into the (8,16384,512)
// image tensor, or -1 if it falls in the zero-padding halo.
// Padded grid is 133x133 with top/left pad = 2 (ph//2 where ph=5).
__device__ __forceinline__ int row_to_image_base(int m) {
    if (m >= M_TOT) return -1;
    int wb = m / LWIN;
    int t  = m - wb * LWIN;
    int b   = wb / (QHW * QHW);
    int rem = wb - b * (QHW * QHW);
    int qi = rem / QHW;
    int qj = rem - qi * QHW;
    int r = qi * 7 + t / 7 - 2;
    int c = qj * 7 + (t % 7) - 2;
    if ((unsigned)r < 128u && (unsigned)c < 128u)
        return (b * 16384 + r * 128 + c) * 512;
    return -1;
}

// =====================================================================
// GEMM 1: qkv[m, n] = sum_k xw[m, k] * Win[n, k] + bin[n]
//   M = 141512, N = 1536, K = 512.  A-load gathers windows from x directly.
// =====================================================================
__global__ __launch_bounds__(256) void qkv_gemm(
    const float* __restrict__ x, const float* __restrict__ w,
    const float* __restrict__ bias)
{
    __shared__ float As[16][128];
    __shared__ float Bs[16][64];
    __shared__ int   rowbase[128];

    const int tid = threadIdx.x;
    const int m0  = blockIdx.y * 128;
    const int n0  = blockIdx.x * 64;

    for (int i = tid; i < 128; i += 256)
        rowbase[i] = row_to_image_base(m0 + i);
    __syncthreads();

    float acc[8][4];
    #pragma unroll
    for (int i = 0; i < 8; i++)
        #pragma unroll
        for (int j = 0; j < 4; j++) acc[i][j] = 0.f;

    const int tr = (tid >> 4) << 3;   // output rows tr..tr+7
    const int tc = (tid & 15) << 2;   // output cols tc..tc+3

    const int arow = tid >> 1;        // A tile: row, 8 k's per thread
    const int ako  = (tid & 1) << 3;
    const int brow = tid >> 2;        // B tile: row, 4 k's per thread
    const int bko  = (tid & 3) << 2;

    for (int k0 = 0; k0 < 512; k0 += 16) {
        // ---- load A (gather) ----
        float4 a0, a1;
        const int base = rowbase[arow];
        if (base >= 0) {
            const float4* p = reinterpret_cast<const float4*>(x + base + k0 + ako);
            a0 = p[0]; a1 = p[1];
        } else {
            a0 = make_float4(0.f, 0.f, 0.f, 0.f);
            a1 = a0;
        }
        As[ako + 0][arow] = a0.x; As[ako + 1][arow] = a0.y;
        As[ako + 2][arow] = a0.z; As[ako + 3][arow] = a0.w;
        As[ako + 4][arow] = a1.x; As[ako + 5][arow] = a1.y;
        As[ako + 6][arow] = a1.z; As[ako + 7][arow] = a1.w;

        // ---- load B ----
        float4 bq = *reinterpret_cast<const float4*>(
            w + (size_t)(n0 + brow) * 512 + k0 + bko);
        Bs[bko + 0][brow] = bq.x; Bs[bko + 1][brow] = bq.y;
        Bs[bko + 2][brow] = bq.z; Bs[bko + 3][brow] = bq.w;
        __syncthreads();

        #pragma unroll
        for (int kk = 0; kk < 16; kk++) {
            float4 aA = *reinterpret_cast<const float4*>(&As[kk][tr]);
            float4 aB = *reinterpret_cast<const float4*>(&As[kk][tr + 4]);
            float4 bb = *reinterpret_cast<const float4*>(&Bs[kk][tc]);
            float av[8] = {aA.x, aA.y, aA.z, aA.w, aB.x, aB.y, aB.z, aB.w};
            float bv[4] = {bb.x, bb.y, bb.z, bb.w};
            #pragma unroll
            for (int i = 0; i < 8; i++)
                #pragma unroll
                for (int j = 0; j < 4; j++)
                    acc[i][j] = fmaf(av[i], bv[j], acc[i][j]);
        }
        __syncthreads();
    }

    const float4 bias4 = *reinterpret_cast<const float4*>(bias + n0 + tc);
    #pragma unroll
    for (int i = 0; i < 8; i++) {
        const int m = m0 + tr + i;
        if (m < M_TOT) {
            float4 o;
            o.x = acc[i][0] + bias4.x; o.y = acc[i][1] + bias4.y;
            o.z = acc[i][2] + bias4.z; o.w = acc[i][3] + bias4.w;
            *reinterpret_cast<float4*>(&g_qkv[(size_t)m * 1536 + n0 + tc]) = o;
        }
    }
}

// =====================================================================
// Attention: one block per (window, head). 49x49 scores, softmax, @V.
// =====================================================================
__global__ __launch_bounds__(64) void attn_kernel(const float* __restrict__ rpe)
{
    __shared__ __align__(16) float qs[49 * 32];
    __shared__ __align__(16) float ks[49 * 32];
    __shared__ __align__(16) float vs[49 * 32];
    __shared__ float bsm[169];

    const int wb  = blockIdx.x;
    const int h   = blockIdx.y;
    const int tid = threadIdx.x;
    const float scale = 0.17677669529663687f;   // 32^-0.5

    for (int i = tid; i < 169; i += 64) bsm[i] = rpe[i * NHEADS + h];

    const float* base = g_qkv + (size_t)wb * (49 * 1536) + h * 32;
    for (int i = tid; i < 49 * 8; i += 64) {
        const int t  = i >> 3;
        const int d4 = (i & 7) << 2;
        const float* p = base + (size_t)t * 1536 + d4;
        float4 q4 = *reinterpret_cast<const float4*>(p);
        q4.x *= scale; q4.y *= scale; q4.z *= scale; q4.w *= scale;
        *reinterpret_cast<float4*>(&qs[t * 32 + d4]) = q4;
        *reinterpret_cast<float4*>(&ks[t * 32 + d4]) =
            *reinterpret_cast<const float4*>(p + 512);
        *reinterpret_cast<float4*>(&vs[t * 32 + d4]) =
            *reinterpret_cast<const float4*>(p + 1024);
    }
    __syncthreads();

    if (tid < 49) {
        const int l = tid;
        float4 qr[8];
        #pragma unroll
        for (int j = 0; j < 8; j++)
            qr[j] = *reinterpret_cast<const float4*>(&qs[l * 32 + j * 4]);
        const int lr = l / 7, lc = l - lr * 7;

        float s[49];
        float mx = -1e30f;
        #pragma unroll
        for (int m2 = 0; m2 < 49; m2++) {
            float acc = 0.f;
            #pragma unroll
            for (int j = 0; j < 8; j++) {
                const float4 kk = *reinterpret_cast<const float4*>(&ks[m2 * 32 + j * 4]);
                acc = fmaf(qr[j].x, kk.x, acc);
                acc = fmaf(qr[j].y, kk.y, acc);
                acc = fmaf(qr[j].z, kk.z, acc);
                acc = fmaf(qr[j].w, kk.w, acc);
            }
            const int mr = m2 / 7, mc = m2 - mr * 7;
            acc += bsm[(lr - mr + 6) * 13 + (lc - mc + 6)];
            s[m2] = acc;
            mx = fmaxf(mx, acc);
        }
        float sum = 0.f;
        #pragma unroll
        for (int m2 = 0; m2 < 49; m2++) {
            const float e = __expf(s[m2] - mx);
            s[m2] = e;
            sum += e;
        }
        const float inv = 1.f / sum;

        float4 o[8];
        #pragma unroll
        for (int j = 0; j < 8; j++) o[j] = make_float4(0.f, 0.f, 0.f, 0.f);
        #pragma unroll
        for (int m2 = 0; m2 < 49; m2++) {
            const float p = s[m2] * inv;
            #pragma unroll
            for (int j = 0; j < 8; j++) {
                const float4 vv = *reinterpret_cast<const float4*>(&vs[m2 * 32 + j * 4]);
                o[j].x = fmaf(p, vv.x, o[j].x);
                o[j].y = fmaf(p, vv.y, o[j].y);
                o[j].z = fmaf(p, vv.z, o[j].z);
                o[j].w = fmaf(p, vv.w, o[j].w);
            }
        }
        float* op = g_att + (size_t)(wb * 49 + l) * 512 + h * 32;
        #pragma unroll
        for (int j = 0; j < 8; j++)
            *reinterpret_cast<float4*>(op + j * 4) = o[j];
    }
}

// =====================================================================
// GEMM 2: y[m, n] = sum_k att[m, k] * Wout[n, k] + bout[n], scatter-crop
//   epilogue writes directly into the (8,16384,512) output.
// =====================================================================
__global__ __launch_bounds__(256) void out_gemm(
    const float* __restrict__ w, const float* __restrict__ bias,
    float* __restrict__ out)
{
    __shared__ float As[16][128];
    __shared__ float Bs[16][64];
    __shared__ int   outbase[128];

    const int tid = threadIdx.x;
    const int m0  = blockIdx.y * 128;
    const int n0  = blockIdx.x * 64;

    for (int i = tid; i < 128; i += 256)
        outbase[i] = row_to_image_base(m0 + i);
    __syncthreads();

    float acc[8][4];
    #pragma unroll
    for (int i = 0; i < 8; i++)
        #pragma unroll
        for (int j = 0; j < 4; j++) acc[i][j] = 0.f;

    const int tr = (tid >> 4) << 3;
    const int tc = (tid & 15) << 2;

    const int arow = tid >> 1;
    const int ako  = (tid & 1) << 3;
    const int brow = tid >> 2;
    const int bko  = (tid & 3) << 2;

    const int am = m0 + arow;

    for (int k0 = 0; k0 < 512; k0 += 16) {
        float4 a0, a1;
        if (am < M_TOT) {
            const float4* p =
                reinterpret_cast<const float4*>(g_att + (size_t)am * 512 + k0 + ako);
            a0 = p[0]; a1 = p[1];
        } else {
            a0 = make_float4(0.f, 0.f, 0.f, 0.f);
            a1 = a0;
        }
        As[ako + 0][arow] = a0.x; As[ako + 1][arow] = a0.y;
        As[ako + 2][arow] = a0.z; As[ako + 3][arow] = a0.w;
        As[ako + 4][arow] = a1.x; As[ako + 5][arow] = a1.y;
        As[ako + 6][arow] = a1.z; As[ako + 7][arow] = a1.w;

        float4 bq = *reinterpret_cast<const float4*>(
            w + (size_t)(n0 + brow) * 512 + k0 + bko);
        Bs[bko + 0][brow] = bq.x; Bs[bko + 1][brow] = bq.y;
        Bs[bko + 2][brow] = bq.z; Bs[bko + 3][brow] = bq.w;
        __syncthreads();

        #pragma unroll
        for (int kk = 0; kk < 16; kk++) {
            float4 aA = *reinterpret_cast<const float4*>(&As[kk][tr]);
            float4 aB = *reinterpret_cast<const float4*>(&As[kk][tr + 4]);
            float4 bb = *reinterpret_cast<const float4*>(&Bs[kk][tc]);
            float av[8] = {aA.x, aA.y, aA.z, aA.w, aB.x, aB.y, aB.z, aB.w};
            float bv[4] = {bb.x, bb.y, bb.z, bb.w};
            #pragma unroll
            for (int i = 0; i < 8; i++)
                #pragma unroll
                for (int j = 0; j < 4; j++)
                    acc[i][j] = fmaf(av[i], bv[j], acc[i][j]);
        }
        __syncthreads();
    }

    const float4 bias4 = *reinterpret_cast<const float4*>(bias + n0 + tc);
    #pragma unroll
    for (int i = 0; i < 8; i++) {
        const int base = outbase[tr + i];
        if (base >= 0) {
            float4 o;
            o.x = acc[i][0] + bias4.x; o.y = acc[i][1] + bias4.y;
            o.z = acc[i][2] + bias4.z; o.w = acc[i][3] + bias4.w;
            *reinterpret_cast<float4*>(&out[(size_t)base + n0 + tc]) = o;
        }
    }
}

// =====================================================================
extern "C" void kernel_launch(void* const* d_in, const int* in_sizes, int n_in,
                              void* d_out, int out_size)
{
    const float* x   = (const float*)d_in[0];
    const float* wi  = (const float*)d_in[1];
    const float* bi  = (const float*)d_in[2];
    const float* wo  = (const float*)d_in[3];
    const float* bo  = (const float*)d_in[4];
    const float* rpe = (const float*)d_in[5];
    float* out = (float*)d_out;

    const int mtiles = (M_TOT + 127) / 128;   // 1106

    qkv_gemm<<<dim3(1536 / 64, mtiles), 256>>>(x, wi, bi);
    attn_kernel<<<dim3(NB, NHEADS), 64>>>(rpe);
    out_gemm<<<dim3(512 / 64, mtiles), 256>>>(wo, bo, out);
}

// round 2
// speedup vs baseline: 2.2425x; 2.2425x over previous
#include <cuda_runtime.h>
#include <cstdint>

// ---------------- problem constants ----------------
#define M_TOT   141512      // 2888 windows * 49 tokens
#define NB      2888        // 8 * 19 * 19
#define QHW     19          // windows per side (ceil(133/7))
#define LWIN    49
#define NHEADS  16

// ---------------- scratch (static device allocations) ----------------
__device__ __align__(16) float g_qkv[217362432];  // M_TOT * 1536
__device__ __align__(16) float g_att[72454144];   // M_TOT * 512

// Map a flattened window-token row m -> float offset into the (8,16384,512)
// image tensor, or -1 if it falls in the zero-padding halo.
__device__ __forceinline__ int row_to_image_base(int m) {
    if (m >= M_TOT) return -1;
    int wb = m / LWIN;
    int t  = m - wb * LWIN;
    int b   = wb / (QHW * QHW);
    int rem = wb - b * (QHW * QHW);
    int qi = rem / QHW;
    int qj = rem - qi * QHW;
    int r = qi * 7 + t / 7 - 2;
    int c = qj * 7 + (t % 7) - 2;
    if ((unsigned)r < 128u && (unsigned)c < 128u)
        return (b * 16384 + r * 128 + c) * 512;
    return -1;
}

__device__ __forceinline__ unsigned f2tf(float f) {
    unsigned u;
    asm("cvt.rna.tf32.f32 %0, %1;" : "=r"(u) : "f"(f));
    return u;
}

__device__ __forceinline__ void ldsm4(unsigned& r0, unsigned& r1, unsigned& r2, unsigned& r3,
                                      uint32_t addr) {
    asm volatile("ldmatrix.sync.aligned.m8n8.x4.shared.b16 {%0,%1,%2,%3}, [%4];"
                 : "=r"(r0), "=r"(r1), "=r"(r2), "=r"(r3) : "r"(addr));
}

__device__ __forceinline__ void mma_tf32(float& d0, float& d1, float& d2, float& d3,
                                         unsigned a0, unsigned a1, unsigned a2, unsigned a3,
                                         unsigned b0, unsigned b1) {
    asm volatile("mma.sync.aligned.m16n8k8.row.col.f32.tf32.tf32.f32 "
                 "{%0,%1,%2,%3}, {%4,%5,%6,%7}, {%8,%9}, {%0,%1,%2,%3};"
                 : "+f"(d0), "+f"(d1), "+f"(d2), "+f"(d3)
                 : "r"(a0), "r"(a1), "r"(a2), "r"(a3), "r"(b0), "r"(b1));
}

// smem geometry (floats): stride 36 per row; A = 128 rows, B = 64 rows, 2 stages
#define SSTR 36
#define A_FLOATS (128 * SSTR)
#define B_FLOATS (64 * SSTR)
#define SMEM_FLOATS (2 * A_FLOATS + 2 * B_FLOATS)   // 13824 floats = 55296 B

// Convert 6 prefetched float4s to tf32 and store to the stage buffers.
__device__ __forceinline__ void sts_stage(float* As, float* Bs,
                                          const float4 av[4], const float4 bv[2],
                                          int tid) {
    const int kq = (tid & 7) << 2;
    #pragma unroll
    for (int i = 0; i < 4; i++) {
        const int row = (tid >> 3) + i * 32;
        uint4 u;
        u.x = f2tf(av[i].x); u.y = f2tf(av[i].y);
        u.z = f2tf(av[i].z); u.w = f2tf(av[i].w);
        *reinterpret_cast<uint4*>(&As[row * SSTR + kq]) = u;
    }
    #pragma unroll
    for (int i = 0; i < 2; i++) {
        const int row = (tid >> 3) + i * 32;
        uint4 u;
        u.x = f2tf(bv[i].x); u.y = f2tf(bv[i].y);
        u.z = f2tf(bv[i].z); u.w = f2tf(bv[i].w);
        *reinterpret_cast<uint4*>(&Bs[row * SSTR + kq]) = u;
    }
}

// Core compute over one stage: 4 k-steps of m16n8k8.
__device__ __forceinline__ void compute_stage(uint32_t a_base, uint32_t b_base,
                                              float acc[2][4][4]) {
    #pragma unroll
    for (int kk = 0; kk < 4; kk++) {
        unsigned af[2][4];
        #pragma unroll
        for (int i = 0; i < 2; i++)
            ldsm4(af[i][0], af[i][1], af[i][2], af[i][3],
                  a_base + (unsigned)((i * 16 * SSTR + kk * 8) * 4));
        unsigned bf[2][4];
        #pragma unroll
        for (int p = 0; p < 2; p++)
            ldsm4(bf[p][0], bf[p][1], bf[p][2], bf[p][3],
                  b_base + (unsigned)((p * 16 * SSTR + kk * 8) * 4));
        #pragma unroll
        for (int i = 0; i < 2; i++)
            #pragma unroll
            for (int j = 0; j < 4; j++) {
                const int p = j >> 1, o = (j & 1) << 1;
                mma_tf32(acc[i][j][0], acc[i][j][1], acc[i][j][2], acc[i][j][3],
                         af[i][0], af[i][1], af[i][2], af[i][3],
                         bf[p][o], bf[p][o + 1]);
            }
    }
}

// Per-thread ldmatrix address offsets (bytes) within a stage buffer.
__device__ __forceinline__ void frag_offsets(int lane, int wm, int wn,
                                             uint32_t& aoff, uint32_t& boff) {
    const int g = lane >> 3, r = lane & 7;
    aoff = (uint32_t)(((wm * 32 + (g & 1) * 8 + r) * SSTR + (g >> 1) * 4) * 4);
    boff = (uint32_t)(((wn * 32 + (g >> 1) * 8 + r) * SSTR + (g & 1) * 4) * 4);
}

// =====================================================================
// GEMM 1 (tf32 tensor-core): qkv = gather(x) @ Win^T + bin
//   M=141512, N=1536, K=512
// =====================================================================
__global__ __launch_bounds__(256) void qkv_gemm_mma(
    const float* __restrict__ x, const float* __restrict__ w,
    const float* __restrict__ bias)
{
    extern __shared__ float smem[];
    float* As[2] = { smem, smem + A_FLOATS };
    float* Bs[2] = { smem + 2 * A_FLOATS, smem + 2 * A_FLOATS + B_FLOATS };

    const int tid  = threadIdx.x;
    const int lane = tid & 31;
    const int wid  = tid >> 5;
    const int wm = wid & 3, wn = wid >> 2;
    const int m0 = blockIdx.y * 128;
    const int n0 = blockIdx.x * 64;

    // per-thread gather bases for the 4 A rows this thread loads
    int abase[4];
    #pragma unroll
    for (int i = 0; i < 4; i++)
        abase[i] = row_to_image_base(m0 + (tid >> 3) + i * 32);
    const int kq = (tid & 7) << 2;
    const float* bsrc = w + (size_t)(n0 + (tid >> 3)) * 512 + kq;

    float acc[2][4][4];
    #pragma unroll
    for (int i = 0; i < 2; i++)
        #pragma unroll
        for (int j = 0; j < 4; j++)
            #pragma unroll
            for (int q = 0; q < 4; q++) acc[i][j][q] = 0.f;

    uint32_t aoff, boff;
    frag_offsets(lane, wm, wn, aoff, boff);
    const float4 z4 = make_float4(0.f, 0.f, 0.f, 0.f);

    // prologue: stage 0
    float4 av[4], bv[2];
    #pragma unroll
    for (int i = 0; i < 4; i++)
        av[i] = (abase[i] >= 0)
              ? *reinterpret_cast<const float4*>(x + abase[i] + kq) : z4;
    #pragma unroll
    for (int i = 0; i < 2; i++)
        bv[i] = *reinterpret_cast<const float4*>(bsrc + (size_t)i * 32 * 512);
    sts_stage(As[0], Bs[0], av, bv, tid);
    __syncthreads();

    #pragma unroll 1
    for (int it = 0; it < 16; ++it) {
        const int cur = it & 1;
        if (it < 15) {
            const int k0 = (it + 1) * 32;
            #pragma unroll
            for (int i = 0; i < 4; i++)
                av[i] = (abase[i] >= 0)
                      ? *reinterpret_cast<const float4*>(x + abase[i] + k0 + kq) : z4;
            #pragma unroll
            for (int i = 0; i < 2; i++)
                bv[i] = *reinterpret_cast<const float4*>(bsrc + k0 + (size_t)i * 32 * 512);
        }
        compute_stage((uint32_t)__cvta_generic_to_shared(As[cur]) + aoff,
                      (uint32_t)__cvta_generic_to_shared(Bs[cur]) + boff, acc);
        if (it < 15) {
            sts_stage(As[cur ^ 1], Bs[cur ^ 1], av, bv, tid);
            __syncthreads();
        }
    }

    // epilogue: bias + store float2 pairs
    #pragma unroll
    for (int i = 0; i < 2; i++) {
        const int r0 = m0 + wm * 32 + i * 16 + (lane >> 2);
        const int r1 = r0 + 8;
        #pragma unroll
        for (int j = 0; j < 4; j++) {
            const int col = n0 + wn * 32 + j * 8 + (lane & 3) * 2;
            const float b0 = bias[col], b1 = bias[col + 1];
            if (r0 < M_TOT) {
                float2 o = make_float2(acc[i][j][0] + b0, acc[i][j][1] + b1);
                *reinterpret_cast<float2*>(&g_qkv[(size_t)r0 * 1536 + col]) = o;
            }
            if (r1 < M_TOT) {
                float2 o = make_float2(acc[i][j][2] + b0, acc[i][j][3] + b1);
                *reinterpret_cast<float2*>(&g_qkv[(size_t)r1 * 1536 + col]) = o;
            }
        }
    }
}

// =====================================================================
// Attention: one block per (window, head). 49x49 scores, softmax, @V. fp32.
// =====================================================================
__global__ __launch_bounds__(64) void attn_kernel(const float* __restrict__ rpe)
{
    __shared__ __align__(16) float qs[49 * 32];
    __shared__ __align__(16) float ks[49 * 32];
    __shared__ __align__(16) float vs[49 * 32];
    __shared__ float bsm[169];

    const int wb  = blockIdx.x;
    const int h   = blockIdx.y;
    const int tid = threadIdx.x;
    const float scale = 0.17677669529663687f;   // 32^-0.5

    for (int i = tid; i < 169; i += 64) bsm[i] = rpe[i * NHEADS + h];

    const float* base = g_qkv + (size_t)wb * (49 * 1536) + h * 32;
    for (int i = tid; i < 49 * 8; i += 64) {
        const int t  = i >> 3;
        const int d4 = (i & 7) << 2;
        const float* p = base + (size_t)t * 1536 + d4;
        float4 q4 = *reinterpret_cast<const float4*>(p);
        q4.x *= scale; q4.y *= scale; q4.z *= scale; q4.w *= scale;
        *reinterpret_cast<float4*>(&qs[t * 32 + d4]) = q4;
        *reinterpret_cast<float4*>(&ks[t * 32 + d4]) =
            *reinterpret_cast<const float4*>(p + 512);
        *reinterpret_cast<float4*>(&vs[t * 32 + d4]) =
            *reinterpret_cast<const float4*>(p + 1024);
    }
    __syncthreads();

    if (tid < 49) {
        const int l = tid;
        float4 qr[8];
        #pragma unroll
        for (int j = 0; j < 8; j++)
            qr[j] = *reinterpret_cast<const float4*>(&qs[l * 32 + j * 4]);
        const int lr = l / 7, lc = l - lr * 7;

        float s[49];
        float mx = -1e30f;
        #pragma unroll
        for (int m2 = 0; m2 < 49; m2++) {
            float acc = 0.f;
            #pragma unroll
            for (int j = 0; j < 8; j++) {
                const float4 kk = *reinterpret_cast<const float4*>(&ks[m2 * 32 + j * 4]);
                acc = fmaf(qr[j].x, kk.x, acc);
                acc = fmaf(qr[j].y, kk.y, acc);
                acc = fmaf(qr[j].z, kk.z, acc);
                acc = fmaf(qr[j].w, kk.w, acc);
            }
            const int mr = m2 / 7, mc = m2 - mr * 7;
            acc += bsm[(lr - mr + 6) * 13 + (lc - mc + 6)];
            s[m2] = acc;
            mx = fmaxf(mx, acc);
        }
        float sum = 0.f;
        #pragma unroll
        for (int m2 = 0; m2 < 49; m2++) {
            const float e = __expf(s[m2] - mx);
            s[m2] = e;
            sum += e;
        }
        const float inv = 1.f / sum;

        float4 o[8];
        #pragma unroll
        for (int j = 0; j < 8; j++) o[j] = make_float4(0.f, 0.f, 0.f, 0.f);
        #pragma unroll
        for (int m2 = 0; m2 < 49; m2++) {
            const float p = s[m2] * inv;
            #pragma unroll
            for (int j = 0; j < 8; j++) {
                const float4 vv = *reinterpret_cast<const float4*>(&vs[m2 * 32 + j * 4]);
                o[j].x = fmaf(p, vv.x, o[j].x);
                o[j].y = fmaf(p, vv.y, o[j].y);
                o[j].z = fmaf(p, vv.z, o[j].z);
                o[j].w = fmaf(p, vv.w, o[j].w);
            }
        }
        float* op = g_att + (size_t)(wb * 49 + l) * 512 + h * 32;
        #pragma unroll
        for (int j = 0; j < 8; j++)
            *reinterpret_cast<float4*>(op + j * 4) = o[j];
    }
}

// =====================================================================
// GEMM 2 (tf32 tensor-core): y = att @ Wout^T + bout, scatter-crop epilogue
//   M=141512, N=512, K=512
// =====================================================================
__global__ __launch_bounds__(256) void out_gemm_mma(
    const float* __restrict__ w, const float* __restrict__ bias,
    float* __restrict__ out)
{
    extern __shared__ float smem[];
    float* As[2] = { smem, smem + A_FLOATS };
    float* Bs[2] = { smem + 2 * A_FLOATS, smem + 2 * A_FLOATS + B_FLOATS };

    const int tid  = threadIdx.x;
    const int lane = tid & 31;
    const int wid  = tid >> 5;
    const int wm = wid & 3, wn = wid >> 2;
    const int m0 = blockIdx.y * 128;
    const int n0 = blockIdx.x * 64;

    const int kq = (tid & 7) << 2;
    int arow[4];
    #pragma unroll
    for (int i = 0; i < 4; i++) arow[i] = m0 + (tid >> 3) + i * 32;
    const float* bsrc = w + (size_t)(n0 + (tid >> 3)) * 512 + kq;

    float acc[2][4][4];
    #pragma unroll
    for (int i = 0; i < 2; i++)
        #pragma unroll
        for (int j = 0; j < 4; j++)
            #pragma unroll
            for (int q = 0; q < 4; q++) acc[i][j][q] = 0.f;

    uint32_t aoff, boff;
    frag_offsets(lane, wm, wn, aoff, boff);
    const float4 z4 = make_float4(0.f, 0.f, 0.f, 0.f);

    float4 av[4], bv[2];
    #pragma unroll
    for (int i = 0; i < 4; i++)
        av[i] = (arow[i] < M_TOT)
              ? *reinterpret_cast<const float4*>(g_att + (size_t)arow[i] * 512 + kq) : z4;
    #pragma unroll
    for (int i = 0; i < 2; i++)
        bv[i] = *reinterpret_cast<const float4*>(bsrc + (size_t)i * 32 * 512);
    sts_stage(As[0], Bs[0], av, bv, tid);
    __syncthreads();

    #pragma unroll 1
    for (int it = 0; it < 16; ++it) {
        const int cur = it & 1;
        if (it < 15) {
            const int k0 = (it + 1) * 32;
            #pragma unroll
            for (int i = 0; i < 4; i++)
                av[i] = (arow[i] < M_TOT)
                      ? *reinterpret_cast<const float4*>(g_att + (size_t)arow[i] * 512 + k0 + kq) : z4;
            #pragma unroll
            for (int i = 0; i < 2; i++)
                bv[i] = *reinterpret_cast<const float4*>(bsrc + k0 + (size_t)i * 32 * 512);
        }
        compute_stage((uint32_t)__cvta_generic_to_shared(As[cur]) + aoff,
                      (uint32_t)__cvta_generic_to_shared(Bs[cur]) + boff, acc);
        if (it < 15) {
            sts_stage(As[cur ^ 1], Bs[cur ^ 1], av, bv, tid);
            __syncthreads();
        }
    }

    // epilogue: bias + scatter-crop into image tensor
    #pragma unroll
    for (int i = 0; i < 2; i++) {
        const int r0 = m0 + wm * 32 + i * 16 + (lane >> 2);
        const int base0 = row_to_image_base(r0);
        const int base1 = row_to_image_base(r0 + 8);
        #pragma unroll
        for (int j = 0; j < 4; j++) {
            const int col = n0 + wn * 32 + j * 8 + (lane & 3) * 2;
            const float b0 = bias[col], b1 = bias[col + 1];
            if (base0 >= 0) {
                float2 o = make_float2(acc[i][j][0] + b0, acc[i][j][1] + b1);
                *reinterpret_cast<float2*>(&out[(size_t)base0 + col]) = o;
            }
            if (base1 >= 0) {
                float2 o = make_float2(acc[i][j][2] + b0, acc[i][j][3] + b1);
                *reinterpret_cast<float2*>(&out[(size_t)base1 + col]) = o;
            }
        }
    }
}

// =====================================================================
extern "C" void kernel_launch(void* const* d_in, const int* in_sizes, int n_in,
                              void* d_out, int out_size)
{
    const float* x   = (const float*)d_in[0];
    const float* wi  = (const float*)d_in[1];
    const float* bi  = (const float*)d_in[2];
    const float* wo  = (const float*)d_in[3];
    const float* bo  = (const float*)d_in[4];
    const float* rpe = (const float*)d_in[5];
    float* out = (float*)d_out;

    static bool attr_done = false;
    if (!attr_done) {
        cudaFuncSetAttribute(qkv_gemm_mma,
            cudaFuncAttributeMaxDynamicSharedMemorySize, SMEM_FLOATS * 4);
        cudaFuncSetAttribute(out_gemm_mma,
            cudaFuncAttributeMaxDynamicSharedMemorySize, SMEM_FLOATS * 4);
        attr_done = true;
    }

    const int mtiles = (M_TOT + 127) / 128;   // 1106

    qkv_gemm_mma<<<dim3(1536 / 64, mtiles), 256, SMEM_FLOATS * 4>>>(x, wi, bi);
    attn_kernel<<<dim3(NB, NHEADS), 64>>>(rpe);
    out_gemm_mma<<<dim3(512 / 64, mtiles), 256, SMEM_FLOATS * 4>>>(wo, bo, out);
}

// round 3
// speedup vs baseline: 2.7457x; 1.2244x over previous
#include <cuda_runtime.h>
#include <cstdint>

// ---------------- problem constants ----------------
#define M_TOT   141512      // 2888 windows * 49 tokens
#define NB      2888        // 8 * 19 * 19
#define QHW     19
#define LWIN    49
#define NHEADS  16

// ---------------- scratch (static device allocations) ----------------
__device__ __align__(16) float g_xtf[67108864];   // x in tf32 bits (8*16384*512)
__device__ __align__(16) float g_wi_tf[786432];   // W_in  tf32 bits (1536*512)
__device__ __align__(16) float g_wo_tf[262144];   // W_out tf32 bits (512*512)
__device__ __align__(16) float g_qkv[217362432];  // M_TOT * 1536 (fp32)
__device__ __align__(16) float g_att[72454144];   // M_TOT * 512  (tf32 bits)

__device__ __forceinline__ int row_to_image_base(int m) {
    if (m >= M_TOT) return -1;
    int wb = m / LWIN;
    int t  = m - wb * LWIN;
    int b   = wb / (QHW * QHW);
    int rem = wb - b * (QHW * QHW);
    int qi = rem / QHW;
    int qj = rem - qi * QHW;
    int r = qi * 7 + t / 7 - 2;
    int c = qj * 7 + (t % 7) - 2;
    if ((unsigned)r < 128u && (unsigned)c < 128u)
        return (b * 16384 + r * 128 + c) * 512;
    return -1;
}

__device__ __forceinline__ unsigned f2tf(float f) {
    unsigned u;
    asm("cvt.rna.tf32.f32 %0, %1;" : "=r"(u) : "f"(f));
    return u;
}

__device__ __forceinline__ void ldsm4(unsigned& r0, unsigned& r1, unsigned& r2, unsigned& r3,
                                      uint32_t addr) {
    asm volatile("ldmatrix.sync.aligned.m8n8.x4.shared.b16 {%0,%1,%2,%3}, [%4];"
                 : "=r"(r0), "=r"(r1), "=r"(r2), "=r"(r3) : "r"(addr));
}

__device__ __forceinline__ void mma_tf32(float& d0, float& d1, float& d2, float& d3,
                                         unsigned a0, unsigned a1, unsigned a2, unsigned a3,
                                         unsigned b0, unsigned b1) {
    asm volatile("mma.sync.aligned.m16n8k8.row.col.f32.tf32.tf32.f32 "
                 "{%0,%1,%2,%3}, {%4,%5,%6,%7}, {%8,%9}, {%0,%1,%2,%3};"
                 : "+f"(d0), "+f"(d1), "+f"(d2), "+f"(d3)
                 : "r"(a0), "r"(a1), "r"(a2), "r"(a3), "r"(b0), "r"(b1));
}

__device__ __forceinline__ void cp16(uint32_t dst, const void* src, int srcsize) {
    asm volatile("cp.async.cg.shared.global [%0], [%1], 16, %2;"
                 :: "r"(dst), "l"(src), "r"(srcsize));
}
__device__ __forceinline__ void cp_commit() { asm volatile("cp.async.commit_group;"); }
__device__ __forceinline__ void cp_wait0()  { asm volatile("cp.async.wait_group 0;" ::: "memory"); }

// smem geometry (floats): stride 36 per row; A = 128 rows, B = 128 rows, 2 stages
#define SSTR   36
#define ABYTES (128 * SSTR * 4)
#define STAGEB (2 * ABYTES)              // A + B per stage = 36864 B
#define SMEMB  (2 * STAGEB)              // 73728 B

// compute one stage: BK=32 -> 4 k-steps of m16n8k8, warp tile 64x32
__device__ __forceinline__ void compute_stage128(uint32_t aB, uint32_t bB,
                                                 float acc[4][4][4]) {
    #pragma unroll
    for (int kk = 0; kk < 4; kk++) {
        unsigned af[4][4];
        #pragma unroll
        for (int i = 0; i < 4; i++)
            ldsm4(af[i][0], af[i][1], af[i][2], af[i][3],
                  aB + (unsigned)((i * 16 * SSTR + kk * 8) * 4));
        unsigned bf[2][4];
        #pragma unroll
        for (int p = 0; p < 2; p++)
            ldsm4(bf[p][0], bf[p][1], bf[p][2], bf[p][3],
                  bB + (unsigned)((p * 16 * SSTR + kk * 8) * 4));
        #pragma unroll
        for (int i = 0; i < 4; i++)
            #pragma unroll
            for (int j = 0; j < 4; j++) {
                const int p = j >> 1, o = (j & 1) << 1;
                mma_tf32(acc[i][j][0], acc[i][j][1], acc[i][j][2], acc[i][j][3],
                         af[i][0], af[i][1], af[i][2], af[i][3],
                         bf[p][o], bf[p][o + 1]);
            }
    }
}

// per-thread ldmatrix byte offsets within a stage's A / B region
__device__ __forceinline__ void frag_offsets(int lane, int wm, int wn,
                                             uint32_t& aoff, uint32_t& boff) {
    const int g = lane >> 3, r = lane & 7;
    aoff = (uint32_t)(((wm * 64 + (g & 1) * 8 + r) * SSTR + (g >> 1) * 4) * 4);
    boff = (uint32_t)(((wn * 32 + (g >> 1) * 8 + r) * SSTR + (g & 1) * 4) * 4);
}

// ---------------- tf32 preconvert ----------------
__global__ void cvt_tf32_kernel(const float* __restrict__ src, int which, int n4) {
    float* dst = (which == 0) ? g_xtf : (which == 1) ? g_wi_tf : g_wo_tf;
    const int stride = gridDim.x * blockDim.x;
    for (int i = blockIdx.x * blockDim.x + threadIdx.x; i < n4; i += stride) {
        float4 v = reinterpret_cast<const float4*>(src)[i];
        uint4 u;
        u.x = f2tf(v.x); u.y = f2tf(v.y); u.z = f2tf(v.z); u.w = f2tf(v.w);
        reinterpret_cast<uint4*>(dst)[i] = u;
    }
}

// =====================================================================
// GEMM 1 (tf32): qkv = gather(x_tf) @ Win^T + bin.  M=141512 N=1536 K=512
// =====================================================================
__global__ __launch_bounds__(256) void qkv_gemm_mma(const float* __restrict__ bias)
{
    extern __shared__ float smem[];
    const int tid = threadIdx.x, lane = tid & 31, wid = tid >> 5;
    const int wm = wid >> 2, wn = wid & 3;
    const int m0 = blockIdx.y * 128, n0 = blockIdx.x * 128;

    const int lrow = tid >> 3;   // 0..31
    const int seg  = tid & 7;    // 16B segment

    int abase[4];
    #pragma unroll
    for (int i = 0; i < 4; i++) abase[i] = row_to_image_base(m0 + lrow + i * 32);
    const float* bsrc = g_wi_tf + (size_t)(n0 + lrow) * 512 + seg * 4;

    const uint32_t s0 = (uint32_t)__cvta_generic_to_shared(smem);
    const uint32_t adst = s0 + (lrow * SSTR + seg * 4) * 4;
    const uint32_t bdst = adst + ABYTES;

    uint32_t aoff, boff;
    frag_offsets(lane, wm, wn, aoff, boff);

    float acc[4][4][4];
    #pragma unroll
    for (int i = 0; i < 4; i++)
        #pragma unroll
        for (int j = 0; j < 4; j++)
            #pragma unroll
            for (int q = 0; q < 4; q++) acc[i][j][q] = 0.f;

    auto issue = [&](int it, int buf) {
        const int k0 = it * 32;
        const uint32_t off = buf * STAGEB;
        #pragma unroll
        for (int i = 0; i < 4; i++) {
            const int sz = (abase[i] >= 0) ? 16 : 0;
            const float* src = (abase[i] >= 0) ? g_xtf + abase[i] + k0 + seg * 4 : g_xtf;
            cp16(adst + off + i * 32 * SSTR * 4, src, sz);
        }
        #pragma unroll
        for (int i = 0; i < 4; i++)
            cp16(bdst + off + i * 32 * SSTR * 4, bsrc + k0 + (size_t)i * 32 * 512, 16);
        cp_commit();
    };

    issue(0, 0);
    #pragma unroll 1
    for (int it = 0; it < 16; ++it) {
        const int cur = it & 1;
        cp_wait0();
        __syncthreads();
        if (it < 15) issue(it + 1, cur ^ 1);
        compute_stage128(s0 + cur * STAGEB + aoff,
                         s0 + cur * STAGEB + ABYTES + boff, acc);
    }

    #pragma unroll
    for (int i = 0; i < 4; i++) {
        const int r0 = m0 + wm * 64 + i * 16 + (lane >> 2);
        const int r1 = r0 + 8;
        #pragma unroll
        for (int j = 0; j < 4; j++) {
            const int col = n0 + wn * 32 + j * 8 + (lane & 3) * 2;
            const float b0 = bias[col], b1 = bias[col + 1];
            if (r0 < M_TOT) {
                float2 o = make_float2(acc[i][j][0] + b0, acc[i][j][1] + b1);
                *reinterpret_cast<float2*>(&g_qkv[(size_t)r0 * 1536 + col]) = o;
            }
            if (r1 < M_TOT) {
                float2 o = make_float2(acc[i][j][2] + b0, acc[i][j][3] + b1);
                *reinterpret_cast<float2*>(&g_qkv[(size_t)r1 * 1536 + col]) = o;
            }
        }
    }
}

// =====================================================================
// Attention: block = (window, head), 128 threads, 2 threads per row.
// Output written as tf32-rounded bits (consumed only by GEMM2).
// =====================================================================
__global__ __launch_bounds__(128) void attn_kernel(const float* __restrict__ rpe)
{
    __shared__ __align__(16) float qs[49 * 32];
    __shared__ __align__(16) float ks[49 * 32];
    __shared__ __align__(16) float vs[49 * 32];
    __shared__ float bsm[169];
    __shared__ float ps[49 * 50];

    const int wb  = blockIdx.x;
    const int h   = blockIdx.y;
    const int tid = threadIdx.x;
    const float scale = 0.17677669529663687f;   // 32^-0.5

    for (int i = tid; i < 169; i += 128) bsm[i] = rpe[i * NHEADS + h];

    const float* base = g_qkv + (size_t)wb * (49 * 1536) + h * 32;
    for (int i = tid; i < 49 * 8; i += 128) {
        const int t  = i >> 3;
        const int d4 = (i & 7) << 2;
        const float* p = base + (size_t)t * 1536 + d4;
        float4 q4 = *reinterpret_cast<const float4*>(p);
        q4.x *= scale; q4.y *= scale; q4.z *= scale; q4.w *= scale;
        *reinterpret_cast<float4*>(&qs[t * 32 + d4]) = q4;
        *reinterpret_cast<float4*>(&ks[t * 32 + d4]) =
            *reinterpret_cast<const float4*>(p + 512);
        *reinterpret_cast<float4*>(&vs[t * 32 + d4]) =
            *reinterpret_cast<const float4*>(p + 1024);
    }
    __syncthreads();

    const bool act = (tid < 98);
    const int l  = act ? (tid >> 1) : 48;
    const int h2 = tid & 1;

    // ---- QK: each lane of a pair handles 16 of the 32 dims ----
    float4 qr[4];
    #pragma unroll
    for (int j = 0; j < 4; j++)
        qr[j] = *reinterpret_cast<const float4*>(&qs[l * 32 + h2 * 16 + j * 4]);

    float s[49];
    #pragma unroll
    for (int m2 = 0; m2 < 49; m2++) {
        float part = 0.f;
        #pragma unroll
        for (int j = 0; j < 4; j++) {
            const float4 kk = *reinterpret_cast<const float4*>(&ks[m2 * 32 + h2 * 16 + j * 4]);
            part = fmaf(qr[j].x, kk.x, part);
            part = fmaf(qr[j].y, kk.y, part);
            part = fmaf(qr[j].z, kk.z, part);
            part = fmaf(qr[j].w, kk.w, part);
        }
        s[m2] = part + __shfl_xor_sync(0xFFFFFFFFu, part, 1);
    }

    const int lr = l / 7, lc = l - lr * 7;
    float mx = -1e30f;
    #pragma unroll
    for (int m2 = 0; m2 < 49; m2++) {
        const int mr = m2 / 7, mc = m2 - mr * 7;
        s[m2] += bsm[(lr - mr + 6) * 13 + (lc - mc + 6)];
        mx = fmaxf(mx, s[m2]);
    }

    // ---- softmax: parity-interleaved exp across the lane pair ----
    float e25[25];
    float sum = 0.f;
    #pragma unroll
    for (int k = 0; k < 25; k++) {
        const int m2 = 2 * k + h2;
        float e = 0.f;
        if (m2 < 49) { e = __expf(s[m2] - mx); sum += e; }
        e25[k] = e;
    }
    sum += __shfl_xor_sync(0xFFFFFFFFu, sum, 1);
    const float inv = 1.f / sum;
    if (act) {
        #pragma unroll
        for (int k = 0; k < 25; k++) {
            const int m2 = 2 * k + h2;
            if (m2 < 49) ps[l * 50 + m2] = e25[k] * inv;
        }
    }
    __syncthreads();

    // ---- PV: lane pair splits the 32 dims ----
    if (act) {
        float4 o[4];
        #pragma unroll
        for (int j = 0; j < 4; j++) o[j] = make_float4(0.f, 0.f, 0.f, 0.f);
        #pragma unroll
        for (int m2 = 0; m2 < 49; m2++) {
            const float p = ps[l * 50 + m2];
            #pragma unroll
            for (int j = 0; j < 4; j++) {
                const float4 vv =
                    *reinterpret_cast<const float4*>(&vs[m2 * 32 + h2 * 16 + j * 4]);
                o[j].x = fmaf(p, vv.x, o[j].x);
                o[j].y = fmaf(p, vv.y, o[j].y);
                o[j].z = fmaf(p, vv.z, o[j].z);
                o[j].w = fmaf(p, vv.w, o[j].w);
            }
        }
        float* op = g_att + (size_t)(wb * 49 + l) * 512 + h * 32 + h2 * 16;
        #pragma unroll
        for (int j = 0; j < 4; j++) {
            uint4 u;
            u.x = f2tf(o[j].x); u.y = f2tf(o[j].y);
            u.z = f2tf(o[j].z); u.w = f2tf(o[j].w);
            *reinterpret_cast<uint4*>(op + j * 4) = u;
        }
    }
}

// =====================================================================
// GEMM 2 (tf32): y = att_tf @ Wout^T + bout, scatter-crop.  N=512 K=512
// =====================================================================
__global__ __launch_bounds__(256) void out_gemm_mma(
    const float* __restrict__ bias, float* __restrict__ out)
{
    extern __shared__ float smem[];
    const int tid = threadIdx.x, lane = tid & 31, wid = tid >> 5;
    const int wm = wid >> 2, wn = wid & 3;
    const int m0 = blockIdx.y * 128, n0 = blockIdx.x * 128;

    const int lrow = tid >> 3;
    const int seg  = tid & 7;

    int arow[4];
    #pragma unroll
    for (int i = 0; i < 4; i++) arow[i] = m0 + lrow + i * 32;
    const float* bsrc = g_wo_tf + (size_t)(n0 + lrow) * 512 + seg * 4;

    const uint32_t s0 = (uint32_t)__cvta_generic_to_shared(smem);
    const uint32_t adst = s0 + (lrow * SSTR + seg * 4) * 4;
    const uint32_t bdst = adst + ABYTES;

    uint32_t aoff, boff;
    frag_offsets(lane, wm, wn, aoff, boff);

    float acc[4][4][4];
    #pragma unroll
    for (int i = 0; i < 4; i++)
        #pragma unroll
        for (int j = 0; j < 4; j++)
            #pragma unroll
            for (int q = 0; q < 4; q++) acc[i][j][q] = 0.f;

    auto issue = [&](int it, int buf) {
        const int k0 = it * 32;
        const uint32_t off = buf * STAGEB;
        #pragma unroll
        for (int i = 0; i < 4; i++) {
            const int sz = (arow[i] < M_TOT) ? 16 : 0;
            const float* src = (arow[i] < M_TOT)
                             ? g_att + (size_t)arow[i] * 512 + k0 + seg * 4 : g_att;
            cp16(adst + off + i * 32 * SSTR * 4, src, sz);
        }
        #pragma unroll
        for (int i = 0; i < 4; i++)
            cp16(bdst + off + i * 32 * SSTR * 4, bsrc + k0 + (size_t)i * 32 * 512, 16);
        cp_commit();
    };

    issue(0, 0);
    #pragma unroll 1
    for (int it = 0; it < 16; ++it) {
        const int cur = it & 1;
        cp_wait0();
        __syncthreads();
        if (it < 15) issue(it + 1, cur ^ 1);
        compute_stage128(s0 + cur * STAGEB + aoff,
                         s0 + cur * STAGEB + ABYTES + boff, acc);
    }

    #pragma unroll
    for (int i = 0; i < 4; i++) {
        const int r0 = m0 + wm * 64 + i * 16 + (lane >> 2);
        const int base0 = row_to_image_base(r0);
        const int base1 = row_to_image_base(r0 + 8);
        #pragma unroll
        for (int j = 0; j < 4; j++) {
            const int col = n0 + wn * 32 + j * 8 + (lane & 3) * 2;
            const float b0 = bias[col], b1 = bias[col + 1];
            if (base0 >= 0) {
                float2 o = make_float2(acc[i][j][0] + b0, acc[i][j][1] + b1);
                *reinterpret_cast<float2*>(&out[(size_t)base0 + col]) = o;
            }
            if (base1 >= 0) {
                float2 o = make_float2(acc[i][j][2] + b0, acc[i][j][3] + b1);
                *reinterpret_cast<float2*>(&out[(size_t)base1 + col]) = o;
            }
        }
    }
}

// =====================================================================
extern "C" void kernel_launch(void* const* d_in, const int* in_sizes, int n_in,
                              void* d_out, int out_size)
{
    const float* x   = (const float*)d_in[0];
    const float* wi  = (const float*)d_in[1];
    const float* bi  = (const float*)d_in[2];
    const float* wo  = (const float*)d_in[3];
    const float* bo  = (const float*)d_in[4];
    const float* rpe = (const float*)d_in[5];
    float* out = (float*)d_out;

    static bool attr_done = false;
    if (!attr_done) {
        cudaFuncSetAttribute(qkv_gemm_mma,
            cudaFuncAttributeMaxDynamicSharedMemorySize, SMEMB);
        cudaFuncSetAttribute(out_gemm_mma,
            cudaFuncAttributeMaxDynamicSharedMemorySize, SMEMB);
        attr_done = true;
    }

    const int mtiles = (M_TOT + 127) / 128;   // 1106

    cvt_tf32_kernel<<<4096, 256>>>(x,  0, 67108864 / 4);
    cvt_tf32_kernel<<<768,  256>>>(wi, 1, 786432 / 4);
    cvt_tf32_kernel<<<256,  256>>>(wo, 2, 262144 / 4);

    qkv_gemm_mma<<<dim3(1536 / 128, mtiles), 256, SMEMB>>>(bi);
    attn_kernel<<<dim3(NB, NHEADS), 128>>>(rpe);
    out_gemm_mma<<<dim3(512 / 128, mtiles), 256, SMEMB>>>(bo, out);
}

// round 4
// speedup vs baseline: 2.7518x; 1.0022x over previous
#include <cuda_runtime.h>
#include <cstdint>

// ---------------- problem constants ----------------
#define M_TOT   141512      // 2888 windows * 49 tokens
#define NB      2888        // 8 * 19 * 19
#define QHW     19
#define LWIN    49
#define NHEADS  16

// ---------------- scratch (static device allocations) ----------------
__device__ __align__(16) float g_xtf[67108864];   // x in tf32 bits (8*16384*512)
__device__ __align__(16) float g_wi_tf[786432];   // W_in  tf32 bits (1536*512)
__device__ __align__(16) float g_wo_tf[262144];   // W_out tf32 bits (512*512)
__device__ __align__(16) float g_qkv[217362432];  // M_TOT * 1536 (fp32)
__device__ __align__(16) float g_att[72454144];   // M_TOT * 512  (tf32 bits)

__device__ __forceinline__ int row_to_image_base(int m) {
    if (m >= M_TOT) return -1;
    int wb = m / LWIN;
    int t  = m - wb * LWIN;
    int b   = wb / (QHW * QHW);
    int rem = wb - b * (QHW * QHW);
    int qi = rem / QHW;
    int qj = rem - qi * QHW;
    int r = qi * 7 + t / 7 - 2;
    int c = qj * 7 + (t % 7) - 2;
    if ((unsigned)r < 128u && (unsigned)c < 128u)
        return (b * 16384 + r * 128 + c) * 512;
    return -1;
}

__device__ __forceinline__ unsigned f2tf(float f) {
    unsigned u;
    asm("cvt.rna.tf32.f32 %0, %1;" : "=r"(u) : "f"(f));
    return u;
}

__device__ __forceinline__ void ldsm4(unsigned& r0, unsigned& r1, unsigned& r2, unsigned& r3,
                                      uint32_t addr) {
    asm volatile("ldmatrix.sync.aligned.m8n8.x4.shared.b16 {%0,%1,%2,%3}, [%4];"
                 : "=r"(r0), "=r"(r1), "=r"(r2), "=r"(r3) : "r"(addr));
}

__device__ __forceinline__ void mma_tf32(float& d0, float& d1, float& d2, float& d3,
                                         unsigned a0, unsigned a1, unsigned a2, unsigned a3,
                                         unsigned b0, unsigned b1) {
    asm volatile("mma.sync.aligned.m16n8k8.row.col.f32.tf32.tf32.f32 "
                 "{%0,%1,%2,%3}, {%4,%5,%6,%7}, {%8,%9}, {%0,%1,%2,%3};"
                 : "+f"(d0), "+f"(d1), "+f"(d2), "+f"(d3)
                 : "r"(a0), "r"(a1), "r"(a2), "r"(a3), "r"(b0), "r"(b1));
}

__device__ __forceinline__ void cp16(uint32_t dst, const void* src, int srcsize) {
    asm volatile("cp.async.cg.shared.global [%0], [%1], 16, %2;"
                 :: "r"(dst), "l"(src), "r"(srcsize));
}
__device__ __forceinline__ void cp_commit() { asm volatile("cp.async.commit_group;"); }
__device__ __forceinline__ void cp_wait0()  { asm volatile("cp.async.wait_group 0;" ::: "memory"); }

// smem geometry (floats): stride 36 per row; A = 128 rows, B = 128 rows, 2 stages
#define SSTR   36
#define ABYTES (128 * SSTR * 4)
#define STAGEB (2 * ABYTES)              // A + B per stage = 36864 B
#define SMEMB  (2 * STAGEB)              // 73728 B

// compute one stage: BK=32 -> 4 k-steps of m16n8k8, warp tile 64x32
__device__ __forceinline__ void compute_stage128(uint32_t aB, uint32_t bB,
                                                 float acc[4][4][4]) {
    #pragma unroll
    for (int kk = 0; kk < 4; kk++) {
        unsigned af[4][4];
        #pragma unroll
        for (int i = 0; i < 4; i++)
            ldsm4(af[i][0], af[i][1], af[i][2], af[i][3],
                  aB + (unsigned)((i * 16 * SSTR + kk * 8) * 4));
        unsigned bf[2][4];
        #pragma unroll
        for (int p = 0; p < 2; p++)
            ldsm4(bf[p][0], bf[p][1], bf[p][2], bf[p][3],
                  bB + (unsigned)((p * 16 * SSTR + kk * 8) * 4));
        #pragma unroll
        for (int i = 0; i < 4; i++)
            #pragma unroll
            for (int j = 0; j < 4; j++) {
                const int p = j >> 1, o = (j & 1) << 1;
                mma_tf32(acc[i][j][0], acc[i][j][1], acc[i][j][2], acc[i][j][3],
                         af[i][0], af[i][1], af[i][2], af[i][3],
                         bf[p][o], bf[p][o + 1]);
            }
    }
}

// per-thread ldmatrix byte offsets within a stage's A / B region
__device__ __forceinline__ void frag_offsets(int lane, int wm, int wn,
                                             uint32_t& aoff, uint32_t& boff) {
    const int g = lane >> 3, r = lane & 7;
    aoff = (uint32_t)(((wm * 64 + (g & 1) * 8 + r) * SSTR + (g >> 1) * 4) * 4);
    boff = (uint32_t)(((wn * 32 + (g >> 1) * 8 + r) * SSTR + (g & 1) * 4) * 4);
}

// ---------------- tf32 preconvert ----------------
__global__ void cvt_tf32_kernel(const float* __restrict__ src, int which, int n4) {
    float* dst = (which == 0) ? g_xtf : (which == 1) ? g_wi_tf : g_wo_tf;
    const int stride = gridDim.x * blockDim.x;
    for (int i = blockIdx.x * blockDim.x + threadIdx.x; i < n4; i += stride) {
        float4 v = reinterpret_cast<const float4*>(src)[i];
        uint4 u;
        u.x = f2tf(v.x); u.y = f2tf(v.y); u.z = f2tf(v.z); u.w = f2tf(v.w);
        reinterpret_cast<uint4*>(dst)[i] = u;
    }
}

// =====================================================================
// GEMM 1 (tf32): qkv = gather(x_tf) @ Win^T + bin.  M=141512 N=1536 K=512
// =====================================================================
__global__ __launch_bounds__(256) void qkv_gemm_mma(const float* __restrict__ bias)
{
    extern __shared__ float smem[];
    const int tid = threadIdx.x, lane = tid & 31, wid = tid >> 5;
    const int wm = wid >> 2, wn = wid & 3;
    const int m0 = blockIdx.y * 128, n0 = blockIdx.x * 128;

    const int lrow = tid >> 3;   // 0..31
    const int seg  = tid & 7;    // 16B segment

    int abase[4];
    #pragma unroll
    for (int i = 0; i < 4; i++) abase[i] = row_to_image_base(m0 + lrow + i * 32);
    const float* bsrc = g_wi_tf + (size_t)(n0 + lrow) * 512 + seg * 4;

    const uint32_t s0 = (uint32_t)__cvta_generic_to_shared(smem);
    const uint32_t adst = s0 + (lrow * SSTR + seg * 4) * 4;
    const uint32_t bdst = adst + ABYTES;

    uint32_t aoff, boff;
    frag_offsets(lane, wm, wn, aoff, boff);

    float acc[4][4][4];
    #pragma unroll
    for (int i = 0; i < 4; i++)
        #pragma unroll
        for (int j = 0; j < 4; j++)
            #pragma unroll
            for (int q = 0; q < 4; q++) acc[i][j][q] = 0.f;

    auto issue = [&](int it, int buf) {
        const int k0 = it * 32;
        const uint32_t off = buf * STAGEB;
        #pragma unroll
        for (int i = 0; i < 4; i++) {
            const int sz = (abase[i] >= 0) ? 16 : 0;
            const float* src = (abase[i] >= 0) ? g_xtf + abase[i] + k0 + seg * 4 : g_xtf;
            cp16(adst + off + i * 32 * SSTR * 4, src, sz);
        }
        #pragma unroll
        for (int i = 0; i < 4; i++)
            cp16(bdst + off + i * 32 * SSTR * 4, bsrc + k0 + (size_t)i * 32 * 512, 16);
        cp_commit();
    };

    issue(0, 0);
    #pragma unroll 1
    for (int it = 0; it < 16; ++it) {
        const int cur = it & 1;
        cp_wait0();
        __syncthreads();
        if (it < 15) issue(it + 1, cur ^ 1);
        compute_stage128(s0 + cur * STAGEB + aoff,
                         s0 + cur * STAGEB + ABYTES + boff, acc);
    }

    #pragma unroll
    for (int i = 0; i < 4; i++) {
        const int r0 = m0 + wm * 64 + i * 16 + (lane >> 2);
        const int r1 = r0 + 8;
        #pragma unroll
        for (int j = 0; j < 4; j++) {
            const int col = n0 + wn * 32 + j * 8 + (lane & 3) * 2;
            const float b0 = bias[col], b1 = bias[col + 1];
            if (r0 < M_TOT) {
                float2 o = make_float2(acc[i][j][0] + b0, acc[i][j][1] + b1);
                *reinterpret_cast<float2*>(&g_qkv[(size_t)r0 * 1536 + col]) = o;
            }
            if (r1 < M_TOT) {
                float2 o = make_float2(acc[i][j][2] + b0, acc[i][j][3] + b1);
                *reinterpret_cast<float2*>(&g_qkv[(size_t)r1 * 1536 + col]) = o;
            }
        }
    }
}

// =====================================================================
// Attention: block = (window, head), 128 threads, 2 threads per row.
// Output written as tf32-rounded bits (consumed only by GEMM2).
// =====================================================================
__global__ __launch_bounds__(128) void attn_kernel(const float* __restrict__ rpe)
{
    __shared__ __align__(16) float qs[49 * 32];
    __shared__ __align__(16) float ks[49 * 32];
    __shared__ __align__(16) float vs[49 * 32];
    __shared__ float bsm[169];
    __shared__ float ps[49 * 50];

    const int wb  = blockIdx.x;
    const int h   = blockIdx.y;
    const int tid = threadIdx.x;
    const float scale = 0.17677669529663687f;   // 32^-0.5

    for (int i = tid; i < 169; i += 128) bsm[i] = rpe[i * NHEADS + h];

    const float* base = g_qkv + (size_t)wb * (49 * 1536) + h * 32;
    for (int i = tid; i < 49 * 8; i += 128) {
        const int t  = i >> 3;
        const int d4 = (i & 7) << 2;
        const float* p = base + (size_t)t * 1536 + d4;
        float4 q4 = *reinterpret_cast<const float4*>(p);
        q4.x *= scale; q4.y *= scale; q4.z *= scale; q4.w *= scale;
        *reinterpret_cast<float4*>(&qs[t * 32 + d4]) = q4;
        *reinterpret_cast<float4*>(&ks[t * 32 + d4]) =
            *reinterpret_cast<const float4*>(p + 512);
        *reinterpret_cast<float4*>(&vs[t * 32 + d4]) =
            *reinterpret_cast<const float4*>(p + 1024);
    }
    __syncthreads();

    const bool act = (tid < 98);
    const int l  = act ? (tid >> 1) : 48;
    const int h2 = tid & 1;

    // ---- QK: each lane of a pair handles 16 of the 32 dims ----
    float4 qr[4];
    #pragma unroll
    for (int j = 0; j < 4; j++)
        qr[j] = *reinterpret_cast<const float4*>(&qs[l * 32 + h2 * 16 + j * 4]);

    float s[49];
    #pragma unroll
    for (int m2 = 0; m2 < 49; m2++) {
        float part = 0.f;
        #pragma unroll
        for (int j = 0; j < 4; j++) {
            const float4 kk = *reinterpret_cast<const float4*>(&ks[m2 * 32 + h2 * 16 + j * 4]);
            part = fmaf(qr[j].x, kk.x, part);
            part = fmaf(qr[j].y, kk.y, part);
            part = fmaf(qr[j].z, kk.z, part);
            part = fmaf(qr[j].w, kk.w, part);
        }
        s[m2] = part + __shfl_xor_sync(0xFFFFFFFFu, part, 1);
    }

    const int lr = l / 7, lc = l - lr * 7;
    float mx = -1e30f;
    #pragma unroll
    for (int m2 = 0; m2 < 49; m2++) {
        const int mr = m2 / 7, mc = m2 - mr * 7;
        s[m2] += bsm[(lr - mr + 6) * 13 + (lc - mc + 6)];
        mx = fmaxf(mx, s[m2]);
    }

    // ---- softmax: parity-interleaved exp across the lane pair ----
    float e25[25];
    float sum = 0.f;
    #pragma unroll
    for (int k = 0; k < 25; k++) {
        const int m2 = 2 * k + h2;
        float e = 0.f;
        if (m2 < 49) { e = __expf(s[m2] - mx); sum += e; }
        e25[k] = e;
    }
    sum += __shfl_xor_sync(0xFFFFFFFFu, sum, 1);
    const float inv = 1.f / sum;
    if (act) {
        #pragma unroll
        for (int k = 0; k < 25; k++) {
            const int m2 = 2 * k + h2;
            if (m2 < 49) ps[l * 50 + m2] = e25[k] * inv;
        }
    }
    __syncthreads();

    // ---- PV: lane pair splits the 32 dims ----
    if (act) {
        float4 o[4];
        #pragma unroll
        for (int j = 0; j < 4; j++) o[j] = make_float4(0.f, 0.f, 0.f, 0.f);
        #pragma unroll
        for (int m2 = 0; m2 < 49; m2++) {
            const float p = ps[l * 50 + m2];
            #pragma unroll
            for (int j = 0; j < 4; j++) {
                const float4 vv =
                    *reinterpret_cast<const float4*>(&vs[m2 * 32 + h2 * 16 + j * 4]);
                o[j].x = fmaf(p, vv.x, o[j].x);
                o[j].y = fmaf(p, vv.y, o[j].y);
                o[j].z = fmaf(p, vv.z, o[j].z);
                o[j].w = fmaf(p, vv.w, o[j].w);
            }
        }
        float* op = g_att + (size_t)(wb * 49 + l) * 512 + h * 32 + h2 * 16;
        #pragma unroll
        for (int j = 0; j < 4; j++) {
            uint4 u;
            u.x = f2tf(o[j].x); u.y = f2tf(o[j].y);
            u.z = f2tf(o[j].z); u.w = f2tf(o[j].w);
            *reinterpret_cast<uint4*>(op + j * 4) = u;
        }
    }
}

// =====================================================================
// GEMM 2 (tf32): y = att_tf @ Wout^T + bout, scatter-crop.  N=512 K=512
// =====================================================================
__global__ __launch_bounds__(256) void out_gemm_mma(
    const float* __restrict__ bias, float* __restrict__ out)
{
    extern __shared__ float smem[];
    const int tid = threadIdx.x, lane = tid & 31, wid = tid >> 5;
    const int wm = wid >> 2, wn = wid & 3;
    const int m0 = blockIdx.y * 128, n0 = blockIdx.x * 128;

    const int lrow = tid >> 3;
    const int seg  = tid & 7;

    int arow[4];
    #pragma unroll
    for (int i = 0; i < 4; i++) arow[i] = m0 + lrow + i * 32;
    const float* bsrc = g_wo_tf + (size_t)(n0 + lrow) * 512 + seg * 4;

    const uint32_t s0 = (uint32_t)__cvta_generic_to_shared(smem);
    const uint32_t adst = s0 + (lrow * SSTR + seg * 4) * 4;
    const uint32_t bdst = adst + ABYTES;

    uint32_t aoff, boff;
    frag_offsets(lane, wm, wn, aoff, boff);

    float acc[4][4][4];
    #pragma unroll
    for (int i = 0; i < 4; i++)
        #pragma unroll
        for (int j = 0; j < 4; j++)
            #pragma unroll
            for (int q = 0; q < 4; q++) acc[i][j][q] = 0.f;

    auto issue = [&](int it, int buf) {
        const int k0 = it * 32;
        const uint32_t off = buf * STAGEB;
        #pragma unroll
        for (int i = 0; i < 4; i++) {
            const int sz = (arow[i] < M_TOT) ? 16 : 0;
            const float* src = (arow[i] < M_TOT)
                             ? g_att + (size_t)arow[i] * 512 + k0 + seg * 4 : g_att;
            cp16(adst + off + i * 32 * SSTR * 4, src, sz);
        }
        #pragma unroll
        for (int i = 0; i < 4; i++)
            cp16(bdst + off + i * 32 * SSTR * 4, bsrc + k0 + (size_t)i * 32 * 512, 16);
        cp_commit();
    };

    issue(0, 0);
    #pragma unroll 1
    for (int it = 0; it < 16; ++it) {
        const int cur = it & 1;
        cp_wait0();
        __syncthreads();
        if (it < 15) issue(it + 1, cur ^ 1);
        compute_stage128(s0 + cur * STAGEB + aoff,
                         s0 + cur * STAGEB + ABYTES + boff, acc);
    }

    #pragma unroll
    for (int i = 0; i < 4; i++) {
        const int r0 = m0 + wm * 64 + i * 16 + (lane >> 2);
        const int base0 = row_to_image_base(r0);
        const int base1 = row_to_image_base(r0 + 8);
        #pragma unroll
        for (int j = 0; j < 4; j++) {
            const int col = n0 + wn * 32 + j * 8 + (lane & 3) * 2;
            const float b0 = bias[col], b1 = bias[col + 1];
            if (base0 >= 0) {
                float2 o = make_float2(acc[i][j][0] + b0, acc[i][j][1] + b1);
                *reinterpret_cast<float2*>(&out[(size_t)base0 + col]) = o;
            }
            if (base1 >= 0) {
                float2 o = make_float2(acc[i][j][2] + b0, acc[i][j][3] + b1);
                *reinterpret_cast<float2*>(&out[(size_t)base1 + col]) = o;
            }
        }
    }
}

// =====================================================================
extern "C" void kernel_launch(void* const* d_in, const int* in_sizes, int n_in,
                              void* d_out, int out_size)
{
    const float* x   = (const float*)d_in[0];
    const float* wi  = (const float*)d_in[1];
    const float* bi  = (const float*)d_in[2];
    const float* wo  = (const float*)d_in[3];
    const float* bo  = (const float*)d_in[4];
    const float* rpe = (const float*)d_in[5];
    float* out = (float*)d_out;

    static bool attr_done = false;
    if (!attr_done) {
        cudaFuncSetAttribute(qkv_gemm_mma,
            cudaFuncAttributeMaxDynamicSharedMemorySize, SMEMB);
        cudaFuncSetAttribute(out_gemm_mma,
            cudaFuncAttributeMaxDynamicSharedMemorySize, SMEMB);
        attr_done = true;
    }

    const int mtiles = (M_TOT + 127) / 128;   // 1106

    cvt_tf32_kernel<<<4096, 256>>>(x,  0, 67108864 / 4);
    cvt_tf32_kernel<<<768,  256>>>(wi, 1, 786432 / 4);
    cvt_tf32_kernel<<<256,  256>>>(wo, 2, 262144 / 4);

    qkv_gemm_mma<<<dim3(1536 / 128, mtiles), 256, SMEMB>>>(bi);
    attn_kernel<<<dim3(NB, NHEADS), 128>>>(rpe);
    out_gemm_mma<<<dim3(512 / 128, mtiles), 256, SMEMB>>>(bo, out);
}

// round 6
// speedup vs baseline: 2.9334x; 1.0660x over previous
#include <cuda_runtime.h>
#include <cstdint>

// ---------------- problem constants ----------------
#define M_TOT   141512      // 2888 windows * 49 tokens
#define NB      2888        // 8 * 19 * 19
#define QHW     19
#define LWIN    49
#define NHEADS  16

// ---------------- scratch (static device allocations) ----------------
__device__ __align__(16) float g_xtf[67108864];   // x in tf32 bits (8*16384*512)
__device__ __align__(16) float g_wi_tf[786432];   // W_in  tf32 bits (1536*512)
__device__ __align__(16) float g_wo_tf[262144];   // W_out tf32 bits (512*512)
__device__ __align__(16) float g_qkv[217362432];  // M_TOT * 1536 (tf32 bits)
__device__ __align__(16) float g_att[72454144];   // M_TOT * 512  (tf32 bits)

__device__ __forceinline__ int row_to_image_base(int m) {
    if (m >= M_TOT) return -1;
    int wb = m / LWIN;
    int t  = m - wb * LWIN;
    int b   = wb / (QHW * QHW);
    int rem = wb - b * (QHW * QHW);
    int qi = rem / QHW;
    int qj = rem - qi * QHW;
    int r = qi * 7 + t / 7 - 2;
    int c = qj * 7 + (t % 7) - 2;
    if ((unsigned)r < 128u && (unsigned)c < 128u)
        return (b * 16384 + r * 128 + c) * 512;
    return -1;
}

__device__ __forceinline__ unsigned f2tf(float f) {
    unsigned u;
    asm("cvt.rna.tf32.f32 %0, %1;" : "=r"(u) : "f"(f));
    return u;
}

__device__ __forceinline__ void ldsm4(unsigned& r0, unsigned& r1, unsigned& r2, unsigned& r3,
                                      uint32_t addr) {
    asm volatile("ldmatrix.sync.aligned.m8n8.x4.shared.b16 {%0,%1,%2,%3}, [%4];"
                 : "=r"(r0), "=r"(r1), "=r"(r2), "=r"(r3) : "r"(addr));
}

__device__ __forceinline__ void mma_tf32(float& d0, float& d1, float& d2, float& d3,
                                         unsigned a0, unsigned a1, unsigned a2, unsigned a3,
                                         unsigned b0, unsigned b1) {
    asm volatile("mma.sync.aligned.m16n8k8.row.col.f32.tf32.tf32.f32 "
                 "{%0,%1,%2,%3}, {%4,%5,%6,%7}, {%8,%9}, {%0,%1,%2,%3};"
                 : "+f"(d0), "+f"(d1), "+f"(d2), "+f"(d3)
                 : "r"(a0), "r"(a1), "r"(a2), "r"(a3), "r"(b0), "r"(b1));
}

__device__ __forceinline__ void cp16(uint32_t dst, const void* src, int srcsize) {
    asm volatile("cp.async.cg.shared.global [%0], [%1], 16, %2;"
                 :: "r"(dst), "l"(src), "r"(srcsize));
}
__device__ __forceinline__ void cp_commit() { asm volatile("cp.async.commit_group;"); }
template <int N>
__device__ __forceinline__ void cp_waitg() {
    asm volatile("cp.async.wait_group %0;" :: "n"(N) : "memory");
}

// smem geometry (floats): stride 36 per row; A = 128 rows, B = 128 rows, 3 stages
#define SSTR   36
#define ABYTES (128 * SSTR * 4)
#define STAGEB (2 * ABYTES)              // A + B per stage = 36864 B
#define NSTAGE 3
#define GSMEMB (NSTAGE * STAGEB)         // 110592 B

// compute one stage: BK=32 -> 4 k-steps of m16n8k8, warp tile 64x32
__device__ __forceinline__ void compute_stage128(uint32_t aB, uint32_t bB,
                                                 float acc[4][4][4]) {
    #pragma unroll
    for (int kk = 0; kk < 4; kk++) {
        unsigned af[4][4];
        #pragma unroll
        for (int i = 0; i < 4; i++)
            ldsm4(af[i][0], af[i][1], af[i][2], af[i][3],
                  aB + (unsigned)((i * 16 * SSTR + kk * 8) * 4));
        unsigned bf[2][4];
        #pragma unroll
        for (int p = 0; p < 2; p++)
            ldsm4(bf[p][0], bf[p][1], bf[p][2], bf[p][3],
                  bB + (unsigned)((p * 16 * SSTR + kk * 8) * 4));
        #pragma unroll
        for (int i = 0; i < 4; i++)
            #pragma unroll
            for (int j = 0; j < 4; j++) {
                const int p = j >> 1, o = (j & 1) << 1;
                mma_tf32(acc[i][j][0], acc[i][j][1], acc[i][j][2], acc[i][j][3],
                         af[i][0], af[i][1], af[i][2], af[i][3],
                         bf[p][o], bf[p][o + 1]);
            }
    }
}

__device__ __forceinline__ void frag_offsets(int lane, int wm, int wn,
                                             uint32_t& aoff, uint32_t& boff) {
    const int g = lane >> 3, r = lane & 7;
    aoff = (uint32_t)(((wm * 64 + (g & 1) * 8 + r) * SSTR + (g >> 1) * 4) * 4);
    boff = (uint32_t)(((wn * 32 + (g >> 1) * 8 + r) * SSTR + (g & 1) * 4) * 4);
}

// ---------------- tf32 preconvert ----------------
__global__ void cvt_tf32_kernel(const float* __restrict__ src, int which, int n4) {
    float* dst = (which == 0) ? g_xtf : (which == 1) ? g_wi_tf : g_wo_tf;
    const int stride = gridDim.x * blockDim.x;
    for (int i = blockIdx.x * blockDim.x + threadIdx.x; i < n4; i += stride) {
        float4 v = reinterpret_cast<const float4*>(src)[i];
        uint4 u;
        u.x = f2tf(v.x); u.y = f2tf(v.y); u.z = f2tf(v.z); u.w = f2tf(v.w);
        reinterpret_cast<uint4*>(dst)[i] = u;
    }
}

// =====================================================================
// GEMM 1 (tf32, 3-stage): qkv = gather(x_tf) @ Win^T + bin -> tf32 bits
// =====================================================================
__global__ __launch_bounds__(256) void qkv_gemm_mma(const float* __restrict__ bias)
{
    extern __shared__ float smem[];
    const int tid = threadIdx.x, lane = tid & 31, wid = tid >> 5;
    const int wm = wid >> 2, wn = wid & 3;
    const int m0 = blockIdx.y * 128, n0 = blockIdx.x * 128;

    const int lrow = tid >> 3;
    const int seg  = tid & 7;

    int abase[4];
    #pragma unroll
    for (int i = 0; i < 4; i++) abase[i] = row_to_image_base(m0 + lrow + i * 32);
    const float* bsrc = g_wi_tf + (size_t)(n0 + lrow) * 512 + seg * 4;

    const uint32_t s0 = (uint32_t)__cvta_generic_to_shared(smem);
    const uint32_t adst = s0 + (lrow * SSTR + seg * 4) * 4;
    const uint32_t bdst = adst + ABYTES;

    uint32_t aoff, boff;
    frag_offsets(lane, wm, wn, aoff, boff);

    float acc[4][4][4];
    #pragma unroll
    for (int i = 0; i < 4; i++)
        #pragma unroll
        for (int j = 0; j < 4; j++)
            #pragma unroll
            for (int q = 0; q < 4; q++) acc[i][j][q] = 0.f;

    auto load = [&](int it, int buf) {
        const int k0 = it * 32;
        const uint32_t off = buf * STAGEB;
        #pragma unroll
        for (int i = 0; i < 4; i++) {
            const int sz = (abase[i] >= 0) ? 16 : 0;
            const float* src = (abase[i] >= 0) ? g_xtf + abase[i] + k0 + seg * 4 : g_xtf;
            cp16(adst + off + i * 32 * SSTR * 4, src, sz);
        }
        #pragma unroll
        for (int i = 0; i < 4; i++)
            cp16(bdst + off + i * 32 * SSTR * 4, bsrc + k0 + (size_t)i * 32 * 512, 16);
        cp_commit();
    };

    load(0, 0);
    load(1, 1);

    #pragma unroll 1
    for (int it = 0; it < 16; ++it) {
        if (it < 15) cp_waitg<1>(); else cp_waitg<0>();
        __syncthreads();
        if (it + 2 < 16) load(it + 2, (it + 2) % NSTAGE);
        const int cur = it % NSTAGE;
        compute_stage128(s0 + cur * STAGEB + aoff,
                         s0 + cur * STAGEB + ABYTES + boff, acc);
    }

    // epilogue: bias in fp32, then round to tf32 bits for downstream consumers
    #pragma unroll
    for (int i = 0; i < 4; i++) {
        const int r0 = m0 + wm * 64 + i * 16 + (lane >> 2);
        const int r1 = r0 + 8;
        #pragma unroll
        for (int j = 0; j < 4; j++) {
            const int col = n0 + wn * 32 + j * 8 + (lane & 3) * 2;
            const float b0 = bias[col], b1 = bias[col + 1];
            if (r0 < M_TOT) {
                uint2 o = make_uint2(f2tf(acc[i][j][0] + b0), f2tf(acc[i][j][1] + b1));
                *reinterpret_cast<uint2*>(&g_qkv[(size_t)r0 * 1536 + col]) = o;
            }
            if (r1 < M_TOT) {
                uint2 o = make_uint2(f2tf(acc[i][j][2] + b0), f2tf(acc[i][j][3] + b1));
                *reinterpret_cast<uint2*>(&g_qkv[(size_t)r1 * 1536 + col]) = o;
            }
        }
    }
}

// =====================================================================
// Attention (tf32 mma): block = (window, head-pair), 128 threads.
//   Per head: S(64x64) = Q(64x32) @ K^T, scalar softmax (49 valid),
//   O(64x32) = P(64x64) @ V (V transposed in smem). Output tf32 bits.
// =====================================================================
#define AT_HSZ 11308    // floats per head: qs 2304 + ks 2304 + vT 2176 + SP 4352 + bias 172
#define AT_SMEMB (2 * AT_HSZ * 4)

__global__ __launch_bounds__(128) void attn_mma(const float* __restrict__ rpe)
{
    extern __shared__ float sm[];
    const int tid  = threadIdx.x;
    const int hh   = tid >> 6;       // which head of the pair
    const int wtid = tid & 63;
    const int wh   = (tid >> 5) & 1; // warp within head
    const int lane = tid & 31;

    const int wb   = blockIdx.x;
    const int head = blockIdx.y * 2 + hh;
    const float scale = 0.17677669529663687f;   // 32^-0.5

    float* qs  = sm + hh * AT_HSZ;        // [64][36]
    float* ks  = qs + 64 * 36;            // [64][36]
    float* vT  = ks + 64 * 36;            // [32][68]  (dim-major, token cols)
    float* SP  = vT + 32 * 68;            // [64][68]  scores then P
    float* bsm = SP + 64 * 68;            // [169]

    // zero vT (padding tokens must be exactly 0, not garbage)
    #pragma unroll 1
    for (int i = wtid; i < 32 * 68 / 4; i += 64)
        reinterpret_cast<float4*>(vT)[i] = make_float4(0.f, 0.f, 0.f, 0.f);

    // load q/k rows + transpose v (all tf32 bits already)
    const float* base = g_qkv + (size_t)wb * (49 * 1536) + head * 32;
    #pragma unroll 1
    for (int i = wtid; i < 392; i += 64) {
        const int t = i >> 3, d4 = (i & 7) << 2;
        const float* p = base + (size_t)t * 1536 + d4;
        *reinterpret_cast<float4*>(&qs[t * 36 + d4]) = *reinterpret_cast<const float4*>(p);
        *reinterpret_cast<float4*>(&ks[t * 36 + d4]) = *reinterpret_cast<const float4*>(p + 512);
        float4 v = *reinterpret_cast<const float4*>(p + 1024);
        vT[(d4 + 0) * 68 + t] = v.x;
        vT[(d4 + 1) * 68 + t] = v.y;
        vT[(d4 + 2) * 68 + t] = v.z;
        vT[(d4 + 3) * 68 + t] = v.w;
    }
    for (int i = wtid; i < 169; i += 64) bsm[i] = rpe[i * NHEADS + head];
    __syncthreads();

    const int g = lane >> 3, r = lane & 7;
    const int mrow = lane >> 2;
    const int c2 = (lane & 3) * 2;

    // ---- QK^T: warp computes S[:, wh*32 .. wh*32+32) ----
    {
        const uint32_t qb = (uint32_t)__cvta_generic_to_shared(qs);
        const uint32_t kb = (uint32_t)__cvta_generic_to_shared(ks);
        const uint32_t aoff = (uint32_t)((((g & 1) * 8 + r) * 36 + (g >> 1) * 4) * 4);
        const uint32_t boff = (uint32_t)(((wh * 32 + (g >> 1) * 8 + r) * 36 + (g & 1) * 4) * 4);

        float acc[4][4][4];
        #pragma unroll
        for (int i = 0; i < 4; i++)
            #pragma unroll
            for (int j = 0; j < 4; j++)
                #pragma unroll
                for (int q = 0; q < 4; q++) acc[i][j][q] = 0.f;

        #pragma unroll
        for (int kk = 0; kk < 4; kk++) {
            unsigned af[4][4];
            #pragma unroll
            for (int mi = 0; mi < 4; mi++)
                ldsm4(af[mi][0], af[mi][1], af[mi][2], af[mi][3],
                      qb + aoff + (unsigned)((mi * 16 * 36 + kk * 8) * 4));
            unsigned bf[2][4];
            #pragma unroll
            for (int p = 0; p < 2; p++)
                ldsm4(bf[p][0], bf[p][1], bf[p][2], bf[p][3],
                      kb + boff + (unsigned)((p * 16 * 36 + kk * 8) * 4));
            #pragma unroll
            for (int mi = 0; mi < 4; mi++)
                #pragma unroll
                for (int nj = 0; nj < 4; nj++) {
                    const int p = nj >> 1, o = (nj & 1) << 1;
                    mma_tf32(acc[mi][nj][0], acc[mi][nj][1], acc[mi][nj][2], acc[mi][nj][3],
                             af[mi][0], af[mi][1], af[mi][2], af[mi][3],
                             bf[p][o], bf[p][o + 1]);
                }
        }

        // store S fragments
        #pragma unroll
        for (int mi = 0; mi < 4; mi++)
            #pragma unroll
            for (int nj = 0; nj < 4; nj++) {
                const int colb = wh * 32 + nj * 8 + c2;
                *reinterpret_cast<float2*>(&SP[(mi * 16 + mrow) * 68 + colb]) =
                    make_float2(acc[mi][nj][0], acc[mi][nj][1]);
                *reinterpret_cast<float2*>(&SP[(mi * 16 + mrow + 8) * 68 + colb]) =
                    make_float2(acc[mi][nj][2], acc[mi][nj][3]);
            }
    }
    __syncthreads();

    // ---- softmax over the 49 valid columns; write P as tf32 bits ----
    if (wtid < 49) {
        const int l = wtid;
        float* row = SP + l * 68;
        const int lr = l / 7, lc = l - lr * 7;
        float s[49];
        float mx = -1e30f;
        #pragma unroll
        for (int m2 = 0; m2 < 49; m2++) {
            const int mr = m2 / 7, mc = m2 - mr * 7;
            const float v = row[m2] * scale + bsm[(lr - mr + 6) * 13 + (lc - mc + 6)];
            s[m2] = v;
            mx = fmaxf(mx, v);
        }
        float sum = 0.f;
        #pragma unroll
        for (int m2 = 0; m2 < 49; m2++) {
            const float e = __expf(s[m2] - mx);
            s[m2] = e;
            sum += e;
        }
        const float inv = 1.f / sum;
        unsigned* urow = reinterpret_cast<unsigned*>(row);
        #pragma unroll
        for (int m2 = 0; m2 < 49; m2++) urow[m2] = f2tf(s[m2] * inv);
        #pragma unroll
        for (int m2 = 49; m2 < 64; m2++) urow[m2] = 0u;
    }
    __syncthreads();

    // ---- P @ V: warp computes O[:, wh*16 .. wh*16+16) ----
    {
        const uint32_t pb = (uint32_t)__cvta_generic_to_shared(SP);
        const uint32_t vb = (uint32_t)__cvta_generic_to_shared(vT);
        const uint32_t aoff = (uint32_t)((((g & 1) * 8 + r) * 68 + (g >> 1) * 4) * 4);
        const uint32_t boff = (uint32_t)(((wh * 16 + (g >> 1) * 8 + r) * 68 + (g & 1) * 4) * 4);

        float o[4][2][4];
        #pragma unroll
        for (int i = 0; i < 4; i++)
            #pragma unroll
            for (int j = 0; j < 2; j++)
                #pragma unroll
                for (int q = 0; q < 4; q++) o[i][j][q] = 0.f;

        #pragma unroll
        for (int kk = 0; kk < 8; kk++) {
            unsigned af[4][4];
            #pragma unroll
            for (int mi = 0; mi < 4; mi++)
                ldsm4(af[mi][0], af[mi][1], af[mi][2], af[mi][3],
                      pb + aoff + (unsigned)((mi * 16 * 68 + kk * 8) * 4));
            unsigned bf[4];
            ldsm4(bf[0], bf[1], bf[2], bf[3], vb + boff + (unsigned)((kk * 8) * 4));
            #pragma unroll
            for (int mi = 0; mi < 4; mi++)
                #pragma unroll
                for (int nj = 0; nj < 2; nj++)
                    mma_tf32(o[mi][nj][0], o[mi][nj][1], o[mi][nj][2], o[mi][nj][3],
                             af[mi][0], af[mi][1], af[mi][2], af[mi][3],
                             bf[nj * 2], bf[nj * 2 + 1]);
        }

        // write O rows < 49 as tf32 bits
        #pragma unroll
        for (int mi = 0; mi < 4; mi++) {
            const int m = mi * 16 + mrow;
            #pragma unroll
            for (int nj = 0; nj < 2; nj++) {
                const int col = head * 32 + wh * 16 + nj * 8 + c2;
                if (m < 49) {
                    uint2 u = make_uint2(f2tf(o[mi][nj][0]), f2tf(o[mi][nj][1]));
                    *reinterpret_cast<uint2*>(&g_att[(size_t)(wb * 49 + m) * 512 + col]) = u;
                }
                if (m + 8 < 49) {
                    uint2 u = make_uint2(f2tf(o[mi][nj][2]), f2tf(o[mi][nj][3]));
                    *reinterpret_cast<uint2*>(&g_att[(size_t)(wb * 49 + m + 8) * 512 + col]) = u;
                }
            }
        }
    }
}

// =====================================================================
// GEMM 2 (tf32, 3-stage): y = att_tf @ Wout^T + bout, scatter-crop
// =====================================================================
__global__ __launch_bounds__(256) void out_gemm_mma(
    const float* __restrict__ bias, float* __restrict__ out)
{
    extern __shared__ float smem[];
    const int tid = threadIdx.x, lane = tid & 31, wid = tid >> 5;
    const int wm = wid >> 2, wn = wid & 3;
    const int m0 = blockIdx.y * 128, n0 = blockIdx.x * 128;

    const int lrow = tid >> 3;
    const int seg  = tid & 7;

    int arow[4];
    #pragma unroll
    for (int i = 0; i < 4; i++) arow[i] = m0 + lrow + i * 32;
    const float* bsrc = g_wo_tf + (size_t)(n0 + lrow) * 512 + seg * 4;

    const uint32_t s0 = (uint32_t)__cvta_generic_to_shared(smem);
    const uint32_t adst = s0 + (lrow * SSTR + seg * 4) * 4;
    const uint32_t bdst = adst + ABYTES;

    uint32_t aoff, boff;
    frag_offsets(lane, wm, wn, aoff, boff);

    float acc[4][4][4];
    #pragma unroll
    for (int i = 0; i < 4; i++)
        #pragma unroll
        for (int j = 0; j < 4; j++)
            #pragma unroll
            for (int q = 0; q < 4; q++) acc[i][j][q] = 0.f;

    auto load = [&](int it, int buf) {
        const int k0 = it * 32;
        const uint32_t off = buf * STAGEB;
        #pragma unroll
        for (int i = 0; i < 4; i++) {
            const int sz = (arow[i] < M_TOT) ? 16 : 0;
            const float* src = (arow[i] < M_TOT)
                             ? g_att + (size_t)arow[i] * 512 + k0 + seg * 4 : g_att;
            cp16(adst + off + i * 32 * SSTR * 4, src, sz);
        }
        #pragma unroll
        for (int i = 0; i < 4; i++)
            cp16(bdst + off + i * 32 * SSTR * 4, bsrc + k0 + (size_t)i * 32 * 512, 16);
        cp_commit();
    };

    load(0, 0);
    load(1, 1);

    #pragma unroll 1
    for (int it = 0; it < 16; ++it) {
        if (it < 15) cp_waitg<1>(); else cp_waitg<0>();
        __syncthreads();
        if (it + 2 < 16) load(it + 2, (it + 2) % NSTAGE);
        const int cur = it % NSTAGE;
        compute_stage128(s0 + cur * STAGEB + aoff,
                         s0 + cur * STAGEB + ABYTES + boff, acc);
    }

    #pragma unroll
    for (int i = 0; i < 4; i++) {
        const int r0 = m0 + wm * 64 + i * 16 + (lane >> 2);
        const int base0 = row_to_image_base(r0);
        const int base1 = row_to_image_base(r0 + 8);
        #pragma unroll
        for (int j = 0; j < 4; j++) {
            const int col = n0 + wn * 32 + j * 8 + (lane & 3) * 2;
            const float b0 = bias[col], b1 = bias[col + 1];
            if (base0 >= 0) {
                float2 o = make_float2(acc[i][j][0] + b0, acc[i][j][1] + b1);
                *reinterpret_cast<float2*>(&out[(size_t)base0 + col]) = o;
            }
            if (base1 >= 0) {
                float2 o = make_float2(acc[i][j][2] + b0, acc[i][j][3] + b1);
                *reinterpret_cast<float2*>(&out[(size_t)base1 + col]) = o;
            }
        }
    }
}

// =====================================================================
extern "C" void kernel_launch(void* const* d_in, const int* in_sizes, int n_in,
                              void* d_out, int out_size)
{
    const float* x   = (const float*)d_in[0];
    const float* wi  = (const float*)d_in[1];
    const float* bi  = (const float*)d_in[2];
    const float* wo  = (const float*)d_in[3];
    const float* bo  = (const float*)d_in[4];
    const float* rpe = (const float*)d_in[5];
    float* out = (float*)d_out;

    static bool attr_done = false;
    if (!attr_done) {
        cudaFuncSetAttribute(qkv_gemm_mma,
            cudaFuncAttributeMaxDynamicSharedMemorySize, GSMEMB);
        cudaFuncSetAttribute(out_gemm_mma,
            cudaFuncAttributeMaxDynamicSharedMemorySize, GSMEMB);
        cudaFuncSetAttribute(attn_mma,
            cudaFuncAttributeMaxDynamicSharedMemorySize, AT_SMEMB);
        attr_done = true;
    }

    const int mtiles = (M_TOT + 127) / 128;   // 1106

    cvt_tf32_kernel<<<4096, 256>>>(x,  0, 67108864 / 4);
    cvt_tf32_kernel<<<768,  256>>>(wi, 1, 786432 / 4);
    cvt_tf32_kernel<<<256,  256>>>(wo, 2, 262144 / 4);

    qkv_gemm_mma<<<dim3(1536 / 128, mtiles), 256, GSMEMB>>>(bi);
    attn_mma<<<dim3(NB, NHEADS / 2), 128, AT_SMEMB>>>(rpe);
    out_gemm_mma<<<dim3(512 / 128, mtiles), 256, GSMEMB>>>(bo, out);
}

// round 7
// speedup vs baseline: 3.2139x; 1.0956x over previous
#include <cuda_runtime.h>
#include <cstdint>

// ---------------- problem constants ----------------
#define M_IMG   131072      // 8 * 128 * 128 image pixels
#define NB      2888        // 8 * 19 * 19 windows
#define QHW     19
#define NHEADS  16

// ---------------- scratch (static device allocations) ----------------
__device__ __align__(16) float g_xtf[67108864];    // x tf32 bits (image layout)
__device__ __align__(16) float g_wi_tf[786432];    // W_in  tf32 bits
__device__ __align__(16) float g_wo_tf[262144];    // W_out tf32 bits
__device__ __align__(16) float g_qkv[201326592];   // M_IMG * 1536 (tf32 bits, image layout)
__device__ __align__(16) float g_att[67108864];    // M_IMG * 512  (tf32 bits, image layout)

__device__ __forceinline__ unsigned f2tf(float f) {
    unsigned u;
    asm("cvt.rna.tf32.f32 %0, %1;" : "=r"(u) : "f"(f));
    return u;
}

__device__ __forceinline__ void ldsm4(unsigned& r0, unsigned& r1, unsigned& r2, unsigned& r3,
                                      uint32_t addr) {
    asm volatile("ldmatrix.sync.aligned.m8n8.x4.shared.b16 {%0,%1,%2,%3}, [%4];"
                 : "=r"(r0), "=r"(r1), "=r"(r2), "=r"(r3) : "r"(addr));
}

__device__ __forceinline__ void mma_tf32(float& d0, float& d1, float& d2, float& d3,
                                         unsigned a0, unsigned a1, unsigned a2, unsigned a3,
                                         unsigned b0, unsigned b1) {
    asm volatile("mma.sync.aligned.m16n8k8.row.col.f32.tf32.tf32.f32 "
                 "{%0,%1,%2,%3}, {%4,%5,%6,%7}, {%8,%9}, {%0,%1,%2,%3};"
                 : "+f"(d0), "+f"(d1), "+f"(d2), "+f"(d3)
                 : "r"(a0), "r"(a1), "r"(a2), "r"(a3), "r"(b0), "r"(b1));
}

__device__ __forceinline__ void cp16(uint32_t dst, const void* src) {
    asm volatile("cp.async.cg.shared.global [%0], [%1], 16;" :: "r"(dst), "l"(src));
}
__device__ __forceinline__ void cp_commit() { asm volatile("cp.async.commit_group;"); }
template <int N>
__device__ __forceinline__ void cp_waitg() {
    asm volatile("cp.async.wait_group %0;" :: "n"(N) : "memory");
}

// smem geometry (floats): stride 36 per row; A = 128 rows, B = 128 rows, 3 stages
#define SSTR   36
#define ABYTES (128 * SSTR * 4)
#define STAGEB (2 * ABYTES)
#define NSTAGE 3
#define GSMEMB (NSTAGE * STAGEB)         // 110592 B

__device__ __forceinline__ void compute_stage128(uint32_t aB, uint32_t bB,
                                                 float acc[4][4][4]) {
    #pragma unroll
    for (int kk = 0; kk < 4; kk++) {
        unsigned af[4][4];
        #pragma unroll
        for (int i = 0; i < 4; i++)
            ldsm4(af[i][0], af[i][1], af[i][2], af[i][3],
                  aB + (unsigned)((i * 16 * SSTR + kk * 8) * 4));
        unsigned bf[2][4];
        #pragma unroll
        for (int p = 0; p < 2; p++)
            ldsm4(bf[p][0], bf[p][1], bf[p][2], bf[p][3],
                  bB + (unsigned)((p * 16 * SSTR + kk * 8) * 4));
        #pragma unroll
        for (int i = 0; i < 4; i++)
            #pragma unroll
            for (int j = 0; j < 4; j++) {
                const int p = j >> 1, o = (j & 1) << 1;
                mma_tf32(acc[i][j][0], acc[i][j][1], acc[i][j][2], acc[i][j][3],
                         af[i][0], af[i][1], af[i][2], af[i][3],
                         bf[p][o], bf[p][o + 1]);
            }
    }
}

__device__ __forceinline__ void frag_offsets(int lane, int wm, int wn,
                                             uint32_t& aoff, uint32_t& boff) {
    const int g = lane >> 3, r = lane & 7;
    aoff = (uint32_t)(((wm * 64 + (g & 1) * 8 + r) * SSTR + (g >> 1) * 4) * 4);
    boff = (uint32_t)(((wn * 32 + (g >> 1) * 8 + r) * SSTR + (g & 1) * 4) * 4);
}

// ---------------- fused tf32 preconvert (x, W_in, W_out) ----------------
#define XN4  16777216
#define WIN4 196608
#define WON4 65536
__global__ void cvt_all(const float* __restrict__ x, const float* __restrict__ wi,
                        const float* __restrict__ wo) {
    const int stride = gridDim.x * blockDim.x;
    for (int i = blockIdx.x * blockDim.x + threadIdx.x;
         i < XN4 + WIN4 + WON4; i += stride) {
        const float4* src;
        uint4* dst;
        if (i < XN4) {
            src = reinterpret_cast<const float4*>(x) + i;
            dst = reinterpret_cast<uint4*>(g_xtf) + i;
        } else if (i < XN4 + WIN4) {
            src = reinterpret_cast<const float4*>(wi) + (i - XN4);
            dst = reinterpret_cast<uint4*>(g_wi_tf) + (i - XN4);
        } else {
            src = reinterpret_cast<const float4*>(wo) + (i - XN4 - WIN4);
            dst = reinterpret_cast<uint4*>(g_wo_tf) + (i - XN4 - WIN4);
        }
        float4 v = *src;
        uint4 u;
        u.x = f2tf(v.x); u.y = f2tf(v.y); u.z = f2tf(v.z); u.w = f2tf(v.w);
        *dst = u;
    }
}

// =====================================================================
// GEMM 1 (tf32, image domain): qkv = x_tf @ Win^T + bin  (M=131072)
// =====================================================================
__global__ __launch_bounds__(256, 2) void qkv_gemm_mma(const float* __restrict__ bias)
{
    extern __shared__ float smem[];
    const int tid = threadIdx.x, lane = tid & 31, wid = tid >> 5;
    const int wm = wid >> 2, wn = wid & 3;
    const int m0 = blockIdx.y * 128, n0 = blockIdx.x * 128;

    const int lrow = tid >> 3;
    const int seg  = tid & 7;

    const float* asrc = g_xtf + (size_t)(m0 + lrow) * 512 + seg * 4;
    const float* bsrc = g_wi_tf + (size_t)(n0 + lrow) * 512 + seg * 4;

    const uint32_t s0 = (uint32_t)__cvta_generic_to_shared(smem);
    const uint32_t adst = s0 + (lrow * SSTR + seg * 4) * 4;
    const uint32_t bdst = adst + ABYTES;

    uint32_t aoff, boff;
    frag_offsets(lane, wm, wn, aoff, boff);

    float acc[4][4][4];
    #pragma unroll
    for (int i = 0; i < 4; i++)
        #pragma unroll
        for (int j = 0; j < 4; j++)
            #pragma unroll
            for (int q = 0; q < 4; q++) acc[i][j][q] = 0.f;

    auto load = [&](int it, int buf) {
        const int k0 = it * 32;
        const uint32_t off = buf * STAGEB;
        #pragma unroll
        for (int i = 0; i < 4; i++)
            cp16(adst + off + i * 32 * SSTR * 4, asrc + k0 + (size_t)i * 32 * 512);
        #pragma unroll
        for (int i = 0; i < 4; i++)
            cp16(bdst + off + i * 32 * SSTR * 4, bsrc + k0 + (size_t)i * 32 * 512);
        cp_commit();
    };

    load(0, 0);
    load(1, 1);

    #pragma unroll 1
    for (int it = 0; it < 16; ++it) {
        if (it < 15) cp_waitg<1>(); else cp_waitg<0>();
        __syncthreads();
        if (it + 2 < 16) load(it + 2, (it + 2) % NSTAGE);
        const int cur = it % NSTAGE;
        compute_stage128(s0 + cur * STAGEB + aoff,
                         s0 + cur * STAGEB + ABYTES + boff, acc);
    }

    #pragma unroll
    for (int i = 0; i < 4; i++) {
        const int r0 = m0 + wm * 64 + i * 16 + (lane >> 2);
        #pragma unroll
        for (int j = 0; j < 4; j++) {
            const int col = n0 + wn * 32 + j * 8 + (lane & 3) * 2;
            const float b0 = bias[col], b1 = bias[col + 1];
            uint2 o0 = make_uint2(f2tf(acc[i][j][0] + b0), f2tf(acc[i][j][1] + b1));
            uint2 o1 = make_uint2(f2tf(acc[i][j][2] + b0), f2tf(acc[i][j][3] + b1));
            *reinterpret_cast<uint2*>(&g_qkv[(size_t)r0 * 1536 + col]) = o0;
            *reinterpret_cast<uint2*>(&g_qkv[(size_t)(r0 + 8) * 1536 + col]) = o1;
        }
    }
}

// =====================================================================
// Attention (tf32 mma, image-domain gather): block = (window, head-pair).
//   Halo tokens (outside the image) have qkv == bias (x=0 rows).
// =====================================================================
#define AT_HSZ 11308
#define AT_SMEMB (2 * AT_HSZ * 4 + 256)

__global__ __launch_bounds__(128) void attn_mma(const float* __restrict__ rpe,
                                                const float* __restrict__ bi)
{
    extern __shared__ float sm[];
    int* s_pix = reinterpret_cast<int*>(sm + 2 * AT_HSZ);   // [49]

    const int tid  = threadIdx.x;
    const int hh   = tid >> 6;
    const int wtid = tid & 63;
    const int wh   = (tid >> 5) & 1;
    const int lane = tid & 31;

    const int wb   = blockIdx.x;
    const int head = blockIdx.y * 2 + hh;
    const float scale = 0.17677669529663687f;   // 32^-0.5

    float* qs  = sm + hh * AT_HSZ;        // [64][36]
    float* ks  = qs + 64 * 36;            // [64][36]
    float* vT  = ks + 64 * 36;            // [32][68]
    float* SP  = vT + 32 * 68;            // [64][68]
    float* bsm = SP + 64 * 68;            // [169]

    // window -> image mapping (token t -> pixel or -1)
    if (tid < 49) {
        const int b  = wb / (QHW * QHW);
        const int rm = wb - b * (QHW * QHW);
        const int qi = rm / QHW, qj = rm - (rm / QHW) * QHW;
        const int r = qi * 7 + tid / 7 - 2;
        const int c = qj * 7 + (tid % 7) - 2;
        s_pix[tid] = ((unsigned)r < 128u && (unsigned)c < 128u)
                   ? (b * 16384 + r * 128 + c) : -1;
    }
    __syncthreads();

    // zero vT (padding tokens must be exactly 0)
    #pragma unroll 1
    for (int i = wtid; i < 32 * 68 / 4; i += 64)
        reinterpret_cast<float4*>(vT)[i] = make_float4(0.f, 0.f, 0.f, 0.f);

    #pragma unroll 1
    for (int i = wtid; i < 392; i += 64) {
        const int t = i >> 3, d4 = (i & 7) << 2;
        const int pix = s_pix[t];
        float4 q4, k4, v4;
        if (pix >= 0) {
            const float* p = g_qkv + (size_t)pix * 1536 + head * 32 + d4;
            q4 = *reinterpret_cast<const float4*>(p);
            k4 = *reinterpret_cast<const float4*>(p + 512);
            v4 = *reinterpret_cast<const float4*>(p + 1024);
        } else {
            const float* bq = bi + head * 32 + d4;
            q4.x = __uint_as_float(f2tf(bq[0]));
            q4.y = __uint_as_float(f2tf(bq[1]));
            q4.z = __uint_as_float(f2tf(bq[2]));
            q4.w = __uint_as_float(f2tf(bq[3]));
            k4.x = __uint_as_float(f2tf(bq[512]));
            k4.y = __uint_as_float(f2tf(bq[513]));
            k4.z = __uint_as_float(f2tf(bq[514]));
            k4.w = __uint_as_float(f2tf(bq[515]));
            v4.x = __uint_as_float(f2tf(bq[1024]));
            v4.y = __uint_as_float(f2tf(bq[1025]));
            v4.z = __uint_as_float(f2tf(bq[1026]));
            v4.w = __uint_as_float(f2tf(bq[1027]));
        }
        *reinterpret_cast<float4*>(&qs[t * 36 + d4]) = q4;
        *reinterpret_cast<float4*>(&ks[t * 36 + d4]) = k4;
        vT[(d4 + 0) * 68 + t] = v4.x;
        vT[(d4 + 1) * 68 + t] = v4.y;
        vT[(d4 + 2) * 68 + t] = v4.z;
        vT[(d4 + 3) * 68 + t] = v4.w;
    }
    for (int i = wtid; i < 169; i += 64) bsm[i] = rpe[i * NHEADS + head];
    __syncthreads();

    const int g = lane >> 3, r = lane & 7;
    const int mrow = lane >> 2;
    const int c2 = (lane & 3) * 2;

    // ---- QK^T ----
    {
        const uint32_t qb = (uint32_t)__cvta_generic_to_shared(qs);
        const uint32_t kb = (uint32_t)__cvta_generic_to_shared(ks);
        const uint32_t aoff = (uint32_t)((((g & 1) * 8 + r) * 36 + (g >> 1) * 4) * 4);
        const uint32_t boff = (uint32_t)(((wh * 32 + (g >> 1) * 8 + r) * 36 + (g & 1) * 4) * 4);

        float acc[4][4][4];
        #pragma unroll
        for (int i = 0; i < 4; i++)
            #pragma unroll
            for (int j = 0; j < 4; j++)
                #pragma unroll
                for (int q = 0; q < 4; q++) acc[i][j][q] = 0.f;

        #pragma unroll
        for (int kk = 0; kk < 4; kk++) {
            unsigned af[4][4];
            #pragma unroll
            for (int mi = 0; mi < 4; mi++)
                ldsm4(af[mi][0], af[mi][1], af[mi][2], af[mi][3],
                      qb + aoff + (unsigned)((mi * 16 * 36 + kk * 8) * 4));
            unsigned bf[2][4];
            #pragma unroll
            for (int p = 0; p < 2; p++)
                ldsm4(bf[p][0], bf[p][1], bf[p][2], bf[p][3],
                      kb + boff + (unsigned)((p * 16 * 36 + kk * 8) * 4));
            #pragma unroll
            for (int mi = 0; mi < 4; mi++)
                #pragma unroll
                for (int nj = 0; nj < 4; nj++) {
                    const int p = nj >> 1, o = (nj & 1) << 1;
                    mma_tf32(acc[mi][nj][0], acc[mi][nj][1], acc[mi][nj][2], acc[mi][nj][3],
                             af[mi][0], af[mi][1], af[mi][2], af[mi][3],
                             bf[p][o], bf[p][o + 1]);
                }
        }

        #pragma unroll
        for (int mi = 0; mi < 4; mi++)
            #pragma unroll
            for (int nj = 0; nj < 4; nj++) {
                const int colb = wh * 32 + nj * 8 + c2;
                *reinterpret_cast<float2*>(&SP[(mi * 16 + mrow) * 68 + colb]) =
                    make_float2(acc[mi][nj][0], acc[mi][nj][1]);
                *reinterpret_cast<float2*>(&SP[(mi * 16 + mrow + 8) * 68 + colb]) =
                    make_float2(acc[mi][nj][2], acc[mi][nj][3]);
            }
    }
    __syncthreads();

    // ---- softmax over 49 valid cols ----
    if (wtid < 49) {
        const int l = wtid;
        float* row = SP + l * 68;
        const int lr = l / 7, lc = l - lr * 7;
        float s[49];
        float mx = -1e30f;
        #pragma unroll
        for (int m2 = 0; m2 < 49; m2++) {
            const int mr = m2 / 7, mc = m2 - mr * 7;
            const float v = row[m2] * scale + bsm[(lr - mr + 6) * 13 + (lc - mc + 6)];
            s[m2] = v;
            mx = fmaxf(mx, v);
        }
        float sum = 0.f;
        #pragma unroll
        for (int m2 = 0; m2 < 49; m2++) {
            const float e = __expf(s[m2] - mx);
            s[m2] = e;
            sum += e;
        }
        const float inv = 1.f / sum;
        unsigned* urow = reinterpret_cast<unsigned*>(row);
        #pragma unroll
        for (int m2 = 0; m2 < 49; m2++) urow[m2] = f2tf(s[m2] * inv);
        #pragma unroll
        for (int m2 = 49; m2 < 64; m2++) urow[m2] = 0u;
    }
    __syncthreads();

    // ---- P @ V ----
    {
        const uint32_t pb = (uint32_t)__cvta_generic_to_shared(SP);
        const uint32_t vb = (uint32_t)__cvta_generic_to_shared(vT);
        const uint32_t aoff = (uint32_t)((((g & 1) * 8 + r) * 68 + (g >> 1) * 4) * 4);
        const uint32_t boff = (uint32_t)(((wh * 16 + (g >> 1) * 8 + r) * 68 + (g & 1) * 4) * 4);

        float o[4][2][4];
        #pragma unroll
        for (int i = 0; i < 4; i++)
            #pragma unroll
            for (int j = 0; j < 2; j++)
                #pragma unroll
                for (int q = 0; q < 4; q++) o[i][j][q] = 0.f;

        #pragma unroll
        for (int kk = 0; kk < 8; kk++) {
            unsigned af[4][4];
            #pragma unroll
            for (int mi = 0; mi < 4; mi++)
                ldsm4(af[mi][0], af[mi][1], af[mi][2], af[mi][3],
                      pb + aoff + (unsigned)((mi * 16 * 68 + kk * 8) * 4));
            unsigned bf[4];
            ldsm4(bf[0], bf[1], bf[2], bf[3], vb + boff + (unsigned)((kk * 8) * 4));
            #pragma unroll
            for (int mi = 0; mi < 4; mi++)
                #pragma unroll
                for (int nj = 0; nj < 2; nj++)
                    mma_tf32(o[mi][nj][0], o[mi][nj][1], o[mi][nj][2], o[mi][nj][3],
                             af[mi][0], af[mi][1], af[mi][2], af[mi][3],
                             bf[nj * 2], bf[nj * 2 + 1]);
        }

        #pragma unroll
        for (int mi = 0; mi < 4; mi++) {
            const int m = mi * 16 + mrow;
            const int pix0 = (m < 49) ? s_pix[m] : -1;
            const int pix1 = (m + 8 < 49) ? s_pix[m + 8] : -1;
            #pragma unroll
            for (int nj = 0; nj < 2; nj++) {
                const int col = head * 32 + wh * 16 + nj * 8 + c2;
                if (pix0 >= 0) {
                    uint2 u = make_uint2(f2tf(o[mi][nj][0]), f2tf(o[mi][nj][1]));
                    *reinterpret_cast<uint2*>(&g_att[(size_t)pix0 * 512 + col]) = u;
                }
                if (pix1 >= 0) {
                    uint2 u = make_uint2(f2tf(o[mi][nj][2]), f2tf(o[mi][nj][3]));
                    *reinterpret_cast<uint2*>(&g_att[(size_t)pix1 * 512 + col]) = u;
                }
            }
        }
    }
}

// =====================================================================
// GEMM 2 (tf32, image domain): out = att_tf @ Wout^T + bout  (direct store)
// =====================================================================
__global__ __launch_bounds__(256, 2) void out_gemm_mma(
    const float* __restrict__ bias, float* __restrict__ out)
{
    extern __shared__ float smem[];
    const int tid = threadIdx.x, lane = tid & 31, wid = tid >> 5;
    const int wm = wid >> 2, wn = wid & 3;
    const int m0 = blockIdx.y * 128, n0 = blockIdx.x * 128;

    const int lrow = tid >> 3;
    const int seg  = tid & 7;

    const float* asrc = g_att + (size_t)(m0 + lrow) * 512 + seg * 4;
    const float* bsrc = g_wo_tf + (size_t)(n0 + lrow) * 512 + seg * 4;

    const uint32_t s0 = (uint32_t)__cvta_generic_to_shared(smem);
    const uint32_t adst = s0 + (lrow * SSTR + seg * 4) * 4;
    const uint32_t bdst = adst + ABYTES;

    uint32_t aoff, boff;
    frag_offsets(lane, wm, wn, aoff, boff);

    float acc[4][4][4];
    #pragma unroll
    for (int i = 0; i < 4; i++)
        #pragma unroll
        for (int j = 0; j < 4; j++)
            #pragma unroll
            for (int q = 0; q < 4; q++) acc[i][j][q] = 0.f;

    auto load = [&](int it, int buf) {
        const int k0 = it * 32;
        const uint32_t off = buf * STAGEB;
        #pragma unroll
        for (int i = 0; i < 4; i++)
            cp16(adst + off + i * 32 * SSTR * 4, asrc + k0 + (size_t)i * 32 * 512);
        #pragma unroll
        for (int i = 0; i < 4; i++)
            cp16(bdst + off + i * 32 * SSTR * 4, bsrc + k0 + (size_t)i * 32 * 512);
        cp_commit();
    };

    load(0, 0);
    load(1, 1);

    #pragma unroll 1
    for (int it = 0; it < 16; ++it) {
        if (it < 15) cp_waitg<1>(); else cp_waitg<0>();
        __syncthreads();
        if (it + 2 < 16) load(it + 2, (it + 2) % NSTAGE);
        const int cur = it % NSTAGE;
        compute_stage128(s0 + cur * STAGEB + aoff,
                         s0 + cur * STAGEB + ABYTES + boff, acc);
    }

    #pragma unroll
    for (int i = 0; i < 4; i++) {
        const int r0 = m0 + wm * 64 + i * 16 + (lane >> 2);
        #pragma unroll
        for (int j = 0; j < 4; j++) {
            const int col = n0 + wn * 32 + j * 8 + (lane & 3) * 2;
            const float b0 = bias[col], b1 = bias[col + 1];
            float2 o0 = make_float2(acc[i][j][0] + b0, acc[i][j][1] + b1);
            float2 o1 = make_float2(acc[i][j][2] + b0, acc[i][j][3] + b1);
            *reinterpret_cast<float2*>(&out[(size_t)r0 * 512 + col]) = o0;
            *reinterpret_cast<float2*>(&out[(size_t)(r0 + 8) * 512 + col]) = o1;
        }
    }
}

// =====================================================================
extern "C" void kernel_launch(void* const* d_in, const int* in_sizes, int n_in,
                              void* d_out, int out_size)
{
    const float* x   = (const float*)d_in[0];
    const float* wi  = (const float*)d_in[1];
    const float* bi  = (const float*)d_in[2];
    const float* wo  = (const float*)d_in[3];
    const float* bo  = (const float*)d_in[4];
    const float* rpe = (const float*)d_in[5];
    float* out = (float*)d_out;

    static bool attr_done = false;
    if (!attr_done) {
        cudaFuncSetAttribute(qkv_gemm_mma,
            cudaFuncAttributeMaxDynamicSharedMemorySize, GSMEMB);
        cudaFuncSetAttribute(out_gemm_mma,
            cudaFuncAttributeMaxDynamicSharedMemorySize, GSMEMB);
        cudaFuncSetAttribute(attn_mma,
            cudaFuncAttributeMaxDynamicSharedMemorySize, AT_SMEMB);
        attr_done = true;
    }

    const int mtiles = M_IMG / 128;   // 1024

    cvt_all<<<4096, 256>>>(x, wi, wo);
    qkv_gemm_mma<<<dim3(1536 / 128, mtiles), 256, GSMEMB>>>(bi);
    attn_mma<<<dim3(NB, NHEADS / 2), 128, AT_SMEMB>>>(rpe, bi);
    out_gemm_mma<<<dim3(512 / 128, mtiles), 256, GSMEMB>>>(bo, out);
}

// round 8
// speedup vs baseline: 3.4486x; 1.0730x over previous
#include <cuda_runtime.h>
#include <cstdint>

// ---------------- problem constants ----------------
#define M_IMG   131072      // 8 * 128 * 128 image pixels
#define NB      2888        // 8 * 19 * 19 windows
#define QHW     19
#define NHEADS  16

// ---------------- scratch (static device allocations) ----------------
__device__ __align__(16) float g_xtf[67108864];    // x tf32 bits (image layout)
__device__ __align__(16) float g_wi_tf[786432];    // W_in  tf32 bits
__device__ __align__(16) float g_wo_tf[262144];    // W_out tf32 bits
__device__ __align__(16) float g_qkv[201326592];   // M_IMG * 1536 (tf32 bits)
__device__ __align__(16) float g_att[67108864];    // M_IMG * 512  (tf32 bits)
__device__ __align__(16) float g_qkvh[1536];       // halo qkv row = tf32(bias)

__device__ __forceinline__ unsigned f2tf(float f) {
    unsigned u;
    asm("cvt.rna.tf32.f32 %0, %1;" : "=r"(u) : "f"(f));
    return u;
}

__device__ __forceinline__ void ldsm4(unsigned& r0, unsigned& r1, unsigned& r2, unsigned& r3,
                                      uint32_t addr) {
    asm volatile("ldmatrix.sync.aligned.m8n8.x4.shared.b16 {%0,%1,%2,%3}, [%4];"
                 : "=r"(r0), "=r"(r1), "=r"(r2), "=r"(r3) : "r"(addr));
}

__device__ __forceinline__ void mma_tf32(float& d0, float& d1, float& d2, float& d3,
                                         unsigned a0, unsigned a1, unsigned a2, unsigned a3,
                                         unsigned b0, unsigned b1) {
    asm volatile("mma.sync.aligned.m16n8k8.row.col.f32.tf32.tf32.f32 "
                 "{%0,%1,%2,%3}, {%4,%5,%6,%7}, {%8,%9}, {%0,%1,%2,%3};"
                 : "+f"(d0), "+f"(d1), "+f"(d2), "+f"(d3)
                 : "r"(a0), "r"(a1), "r"(a2), "r"(a3), "r"(b0), "r"(b1));
}

__device__ __forceinline__ void cp16(uint32_t dst, const void* src) {
    asm volatile("cp.async.cg.shared.global [%0], [%1], 16;" :: "r"(dst), "l"(src));
}
__device__ __forceinline__ void cp_commit() { asm volatile("cp.async.commit_group;"); }
template <int N>
__device__ __forceinline__ void cp_waitg() {
    asm volatile("cp.async.wait_group %0;" :: "n"(N) : "memory");
}

// smem: stride 36 floats/row; A=128 rows, B=128 rows per stage, 3 stages
#define SSTR   36
#define ABYTES (128 * SSTR * 4)          // 18432
#define STAGEB (2 * ABYTES)              // 36864
#define NSTAGE 3
#define GSMEMB (NSTAGE * STAGEB)         // 110592 (2 CTAs/SM)

// one stage, warp tile 64x64: 4 k-steps, per k-step 8 ldsm4 -> 32 MMA
__device__ __forceinline__ void compute_stage64(uint32_t aB, uint32_t bB,
                                                float acc[4][8][4]) {
    #pragma unroll
    for (int kk = 0; kk < 4; kk++) {
        unsigned af[4][4];
        #pragma unroll
        for (int mi = 0; mi < 4; mi++)
            ldsm4(af[mi][0], af[mi][1], af[mi][2], af[mi][3],
                  aB + (unsigned)((mi * 16 * SSTR + kk * 8) * 4));
        unsigned bf[4][4];
        #pragma unroll
        for (int p = 0; p < 4; p++)
            ldsm4(bf[p][0], bf[p][1], bf[p][2], bf[p][3],
                  bB + (unsigned)((p * 16 * SSTR + kk * 8) * 4));
        #pragma unroll
        for (int mi = 0; mi < 4; mi++)
            #pragma unroll
            for (int nj = 0; nj < 8; nj++) {
                const int p = nj >> 1, o = (nj & 1) << 1;
                mma_tf32(acc[mi][nj][0], acc[mi][nj][1], acc[mi][nj][2], acc[mi][nj][3],
                         af[mi][0], af[mi][1], af[mi][2], af[mi][3],
                         bf[p][o], bf[p][o + 1]);
            }
    }
}

__device__ __forceinline__ void frag_offsets64(int lane, int wm, int wn,
                                               uint32_t& aoff, uint32_t& boff) {
    const int g = lane >> 3, r = lane & 7;
    aoff = (uint32_t)(((wm * 64 + (g & 1) * 8 + r) * SSTR + (g >> 1) * 4) * 4);
    boff = (uint32_t)(((wn * 64 + (g >> 1) * 8 + r) * SSTR + (g & 1) * 4) * 4);
}

// ---------------- fused tf32 preconvert ----------------
#define XN4  16777216
#define WIN4 196608
#define WON4 65536
__global__ void cvt_all(const float* __restrict__ x, const float* __restrict__ wi,
                        const float* __restrict__ wo, const float* __restrict__ bi) {
    if (blockIdx.x == 0) {
        for (int i = threadIdx.x; i < 1536; i += 256)
            reinterpret_cast<unsigned*>(g_qkvh)[i] = f2tf(bi[i]);
    }
    const int stride = gridDim.x * blockDim.x;
    for (int i = blockIdx.x * blockDim.x + threadIdx.x;
         i < XN4 + WIN4 + WON4; i += stride) {
        const float4* src;
        uint4* dst;
        if (i < XN4) {
            src = reinterpret_cast<const float4*>(x) + i;
            dst = reinterpret_cast<uint4*>(g_xtf) + i;
        } else if (i < XN4 + WIN4) {
            src = reinterpret_cast<const float4*>(wi) + (i - XN4);
            dst = reinterpret_cast<uint4*>(g_wi_tf) + (i - XN4);
        } else {
            src = reinterpret_cast<const float4*>(wo) + (i - XN4 - WIN4);
            dst = reinterpret_cast<uint4*>(g_wo_tf) + (i - XN4 - WIN4);
        }
        float4 v = *src;
        uint4 u;
        u.x = f2tf(v.x); u.y = f2tf(v.y); u.z = f2tf(v.z); u.w = f2tf(v.w);
        *dst = u;
    }
}

// =====================================================================
// GEMM 1 (tf32, 64x64 warp tiles): qkv = x_tf @ Win^T + bin
// =====================================================================
__global__ __launch_bounds__(128, 2) void qkv_gemm_mma(const float* __restrict__ bias)
{
    extern __shared__ float smem[];
    const int tid = threadIdx.x, lane = tid & 31, wid = tid >> 5;
    const int wm = wid >> 1, wn = wid & 1;
    const int m0 = blockIdx.y * 128, n0 = blockIdx.x * 128;

    const int lrow = tid >> 3;       // 0..15
    const int seg  = tid & 7;

    const float* asrc = g_xtf + (size_t)(m0 + lrow) * 512 + seg * 4;
    const float* bsrc = g_wi_tf + (size_t)(n0 + lrow) * 512 + seg * 4;

    const uint32_t s0 = (uint32_t)__cvta_generic_to_shared(smem);
    const uint32_t adst = s0 + (lrow * SSTR + seg * 4) * 4;
    const uint32_t bdst = adst + ABYTES;

    uint32_t aoff, boff;
    frag_offsets64(lane, wm, wn, aoff, boff);

    float acc[4][8][4];
    #pragma unroll
    for (int i = 0; i < 4; i++)
        #pragma unroll
        for (int j = 0; j < 8; j++)
            #pragma unroll
            for (int q = 0; q < 4; q++) acc[i][j][q] = 0.f;

    auto load = [&](int it, int buf) {
        const int k0 = it * 32;
        const uint32_t off = buf * STAGEB;
        #pragma unroll
        for (int i = 0; i < 8; i++)
            cp16(adst + off + i * 16 * SSTR * 4, asrc + k0 + (size_t)i * 16 * 512);
        #pragma unroll
        for (int i = 0; i < 8; i++)
            cp16(bdst + off + i * 16 * SSTR * 4, bsrc + k0 + (size_t)i * 16 * 512);
        cp_commit();
    };

    load(0, 0);
    load(1, 1);

    #pragma unroll 1
    for (int it = 0; it < 16; ++it) {
        if (it < 15) cp_waitg<1>(); else cp_waitg<0>();
        __syncthreads();
        if (it + 2 < 16) load(it + 2, (it + 2) % NSTAGE);
        const int cur = it % NSTAGE;
        compute_stage64(s0 + cur * STAGEB + aoff,
                        s0 + cur * STAGEB + ABYTES + boff, acc);
    }

    #pragma unroll
    for (int i = 0; i < 4; i++) {
        const int r0 = m0 + wm * 64 + i * 16 + (lane >> 2);
        #pragma unroll
        for (int j = 0; j < 8; j++) {
            const int col = n0 + wn * 64 + j * 8 + (lane & 3) * 2;
            const float b0 = bias[col], b1 = bias[col + 1];
            uint2 o0 = make_uint2(f2tf(acc[i][j][0] + b0), f2tf(acc[i][j][1] + b1));
            uint2 o1 = make_uint2(f2tf(acc[i][j][2] + b0), f2tf(acc[i][j][3] + b1));
            *reinterpret_cast<uint2*>(&g_qkv[(size_t)r0 * 1536 + col]) = o0;
            *reinterpret_cast<uint2*>(&g_qkv[(size_t)(r0 + 8) * 1536 + col]) = o1;
        }
    }
}

// =====================================================================
// Attention (tf32 mma): one block per (window, head), 64 threads.
// =====================================================================
#define AT_HSZ 11308
#define AT_SMEMB ((AT_HSZ + 64) * 4)

__global__ __launch_bounds__(64) void attn_mma(const float* __restrict__ rpe)
{
    extern __shared__ float sm[];
    int* s_pix = reinterpret_cast<int*>(sm + AT_HSZ);   // [49]

    const int tid  = threadIdx.x;
    const int wh   = tid >> 5;
    const int lane = tid & 31;

    const int wb   = blockIdx.x;
    const int head = blockIdx.y;
    const float scale = 0.17677669529663687f;   // 32^-0.5

    float* qs  = sm;                      // [64][36]
    float* ks  = qs + 64 * 36;            // [64][36]
    float* vT  = ks + 64 * 36;            // [32][68]
    float* SP  = vT + 32 * 68;            // [64][68]
    float* bsm = SP + 64 * 68;            // [169]

    if (tid < 49) {
        const int b  = wb / (QHW * QHW);
        const int rm = wb - b * (QHW * QHW);
        const int qi = rm / QHW, qj = rm - (rm / QHW) * QHW;
        const int r = qi * 7 + tid / 7 - 2;
        const int c = qj * 7 + (tid % 7) - 2;
        s_pix[tid] = ((unsigned)r < 128u && (unsigned)c < 128u)
                   ? (b * 16384 + r * 128 + c) : -1;
    }
    __syncthreads();

    // zero vT (padding tokens must be exactly 0)
    #pragma unroll 1
    for (int i = tid; i < 32 * 68 / 4; i += 64)
        reinterpret_cast<float4*>(vT)[i] = make_float4(0.f, 0.f, 0.f, 0.f);

    #pragma unroll 1
    for (int i = tid; i < 392; i += 64) {
        const int t = i >> 3, d4 = (i & 7) << 2;
        const int pix = s_pix[t];
        const float* p = (pix >= 0) ? g_qkv + (size_t)pix * 1536 + head * 32 + d4
                                    : g_qkvh + head * 32 + d4;
        float4 q4 = *reinterpret_cast<const float4*>(p);
        float4 k4 = *reinterpret_cast<const float4*>(p + 512);
        float4 v4 = *reinterpret_cast<const float4*>(p + 1024);
        *reinterpret_cast<float4*>(&qs[t * 36 + d4]) = q4;
        *reinterpret_cast<float4*>(&ks[t * 36 + d4]) = k4;
        vT[(d4 + 0) * 68 + t] = v4.x;
        vT[(d4 + 1) * 68 + t] = v4.y;
        vT[(d4 + 2) * 68 + t] = v4.z;
        vT[(d4 + 3) * 68 + t] = v4.w;
    }
    for (int i = tid; i < 169; i += 64) bsm[i] = rpe[i * NHEADS + head];
    __syncthreads();

    const int g = lane >> 3, r = lane & 7;
    const int mrow = lane >> 2;
    const int c2 = (lane & 3) * 2;

    // ---- QK^T: warp wh computes cols [wh*32, wh*32+32) ----
    {
        const uint32_t qb = (uint32_t)__cvta_generic_to_shared(qs);
        const uint32_t kb = (uint32_t)__cvta_generic_to_shared(ks);
        const uint32_t aoff = (uint32_t)((((g & 1) * 8 + r) * 36 + (g >> 1) * 4) * 4);
        const uint32_t boff = (uint32_t)(((wh * 32 + (g >> 1) * 8 + r) * 36 + (g & 1) * 4) * 4);

        float acc[4][4][4];
        #pragma unroll
        for (int i = 0; i < 4; i++)
            #pragma unroll
            for (int j = 0; j < 4; j++)
                #pragma unroll
                for (int q = 0; q < 4; q++) acc[i][j][q] = 0.f;

        #pragma unroll
        for (int kk = 0; kk < 4; kk++) {
            unsigned af[4][4];
            #pragma unroll
            for (int mi = 0; mi < 4; mi++)
                ldsm4(af[mi][0], af[mi][1], af[mi][2], af[mi][3],
                      qb + aoff + (unsigned)((mi * 16 * 36 + kk * 8) * 4));
            unsigned bf[2][4];
            #pragma unroll
            for (int p = 0; p < 2; p++)
                ldsm4(bf[p][0], bf[p][1], bf[p][2], bf[p][3],
                      kb + boff + (unsigned)((p * 16 * 36 + kk * 8) * 4));
            #pragma unroll
            for (int mi = 0; mi < 4; mi++)
                #pragma unroll
                for (int nj = 0; nj < 4; nj++) {
                    const int p = nj >> 1, o = (nj & 1) << 1;
                    mma_tf32(acc[mi][nj][0], acc[mi][nj][1], acc[mi][nj][2], acc[mi][nj][3],
                             af[mi][0], af[mi][1], af[mi][2], af[mi][3],
                             bf[p][o], bf[p][o + 1]);
                }
        }

        #pragma unroll
        for (int mi = 0; mi < 4; mi++)
            #pragma unroll
            for (int nj = 0; nj < 4; nj++) {
                const int colb = wh * 32 + nj * 8 + c2;
                *reinterpret_cast<float2*>(&SP[(mi * 16 + mrow) * 68 + colb]) =
                    make_float2(acc[mi][nj][0], acc[mi][nj][1]);
                *reinterpret_cast<float2*>(&SP[(mi * 16 + mrow + 8) * 68 + colb]) =
                    make_float2(acc[mi][nj][2], acc[mi][nj][3]);
            }
    }
    __syncthreads();

    // ---- softmax over 49 valid cols ----
    if (tid < 49) {
        const int l = tid;
        float* row = SP + l * 68;
        const int lr = l / 7, lc = l - lr * 7;
        float s[49];
        float mx = -1e30f;
        #pragma unroll
        for (int m2 = 0; m2 < 49; m2++) {
            const int mr = m2 / 7, mc = m2 - mr * 7;
            const float v = row[m2] * scale + bsm[(lr - mr + 6) * 13 + (lc - mc + 6)];
            s[m2] = v;
            mx = fmaxf(mx, v);
        }
        float sum = 0.f;
        #pragma unroll
        for (int m2 = 0; m2 < 49; m2++) {
            const float e = __expf(s[m2] - mx);
            s[m2] = e;
            sum += e;
        }
        const float inv = 1.f / sum;
        unsigned* urow = reinterpret_cast<unsigned*>(row);
        #pragma unroll
        for (int m2 = 0; m2 < 49; m2++) urow[m2] = f2tf(s[m2] * inv);
        #pragma unroll
        for (int m2 = 49; m2 < 64; m2++) urow[m2] = 0u;
    }
    __syncthreads();

    // ---- P @ V: warp wh computes cols [wh*16, wh*16+16) ----
    {
        const uint32_t pb = (uint32_t)__cvta_generic_to_shared(SP);
        const uint32_t vb = (uint32_t)__cvta_generic_to_shared(vT);
        const uint32_t aoff = (uint32_t)((((g & 1) * 8 + r) * 68 + (g >> 1) * 4) * 4);
        const uint32_t boff = (uint32_t)(((wh * 16 + (g >> 1) * 8 + r) * 68 + (g & 1) * 4) * 4);

        float o[4][2][4];
        #pragma unroll
        for (int i = 0; i < 4; i++)
            #pragma unroll
            for (int j = 0; j < 2; j++)
                #pragma unroll
                for (int q = 0; q < 4; q++) o[i][j][q] = 0.f;

        #pragma unroll
        for (int kk = 0; kk < 8; kk++) {
            unsigned af[4][4];
            #pragma unroll
            for (int mi = 0; mi < 4; mi++)
                ldsm4(af[mi][0], af[mi][1], af[mi][2], af[mi][3],
                      pb + aoff + (unsigned)((mi * 16 * 68 + kk * 8) * 4));
            unsigned bf[4];
            ldsm4(bf[0], bf[1], bf[2], bf[3], vb + boff + (unsigned)((kk * 8) * 4));
            #pragma unroll
            for (int mi = 0; mi < 4; mi++)
                #pragma unroll
                for (int nj = 0; nj < 2; nj++)
                    mma_tf32(o[mi][nj][0], o[mi][nj][1], o[mi][nj][2], o[mi][nj][3],
                             af[mi][0], af[mi][1], af[mi][2], af[mi][3],
                             bf[nj * 2], bf[nj * 2 + 1]);
        }

        #pragma unroll
        for (int mi = 0; mi < 4; mi++) {
            const int m = mi * 16 + mrow;
            const int pix0 = (m < 49) ? s_pix[m] : -1;
            const int pix1 = (m + 8 < 49) ? s_pix[m + 8] : -1;
            #pragma unroll
            for (int nj = 0; nj < 2; nj++) {
                const int col = head * 32 + wh * 16 + nj * 8 + c2;
                if (pix0 >= 0) {
                    uint2 u = make_uint2(f2tf(o[mi][nj][0]), f2tf(o[mi][nj][1]));
                    *reinterpret_cast<uint2*>(&g_att[(size_t)pix0 * 512 + col]) = u;
                }
                if (pix1 >= 0) {
                    uint2 u = make_uint2(f2tf(o[mi][nj][2]), f2tf(o[mi][nj][3]));
                    *reinterpret_cast<uint2*>(&g_att[(size_t)pix1 * 512 + col]) = u;
                }
            }
        }
    }
}

// =====================================================================
// GEMM 2 (tf32, 64x64 warp tiles): out = att_tf @ Wout^T + bout
// =====================================================================
__global__ __launch_bounds__(128, 2) void out_gemm_mma(
    const float* __restrict__ bias, float* __restrict__ out)
{
    extern __shared__ float smem[];
    const int tid = threadIdx.x, lane = tid & 31, wid = tid >> 5;
    const int wm = wid >> 1, wn = wid & 1;
    const int m0 = blockIdx.y * 128, n0 = blockIdx.x * 128;

    const int lrow = tid >> 3;
    const int seg  = tid & 7;

    const float* asrc = g_att + (size_t)(m0 + lrow) * 512 + seg * 4;
    const float* bsrc = g_wo_tf + (size_t)(n0 + lrow) * 512 + seg * 4;

    const uint32_t s0 = (uint32_t)__cvta_generic_to_shared(smem);
    const uint32_t adst = s0 + (lrow * SSTR + seg * 4) * 4;
    const uint32_t bdst = adst + ABYTES;

    uint32_t aoff, boff;
    frag_offsets64(lane, wm, wn, aoff, boff);

    float acc[4][8][4];
    #pragma unroll
    for (int i = 0; i < 4; i++)
        #pragma unroll
        for (int j = 0; j < 8; j++)
            #pragma unroll
            for (int q = 0; q < 4; q++) acc[i][j][q] = 0.f;

    auto load = [&](int it, int buf) {
        const int k0 = it * 32;
        const uint32_t off = buf * STAGEB;
        #pragma unroll
        for (int i = 0; i < 8; i++)
            cp16(adst + off + i * 16 * SSTR * 4, asrc + k0 + (size_t)i * 16 * 512);
        #pragma unroll
        for (int i = 0; i < 8; i++)
            cp16(bdst + off + i * 16 * SSTR * 4, bsrc + k0 + (size_t)i * 16 * 512);
        cp_commit();
    };

    load(0, 0);
    load(1, 1);

    #pragma unroll 1
    for (int it = 0; it < 16; ++it) {
        if (it < 15) cp_waitg<1>(); else cp_waitg<0>();
        __syncthreads();
        if (it + 2 < 16) load(it + 2, (it + 2) % NSTAGE);
        const int cur = it % NSTAGE;
        compute_stage64(s0 + cur * STAGEB + aoff,
                        s0 + cur * STAGEB + ABYTES + boff, acc);
    }

    #pragma unroll
    for (int i = 0; i < 4; i++) {
        const int r0 = m0 + wm * 64 + i * 16 + (lane >> 2);
        #pragma unroll
        for (int j = 0; j < 8; j++) {
            const int col = n0 + wn * 64 + j * 8 + (lane & 3) * 2;
            const float b0 = bias[col], b1 = bias[col + 1];
            float2 o0 = make_float2(acc[i][j][0] + b0, acc[i][j][1] + b1);
            float2 o1 = make_float2(acc[i][j][2] + b0, acc[i][j][3] + b1);
            *reinterpret_cast<float2*>(&out[(size_t)r0 * 512 + col]) = o0;
            *reinterpret_cast<float2*>(&out[(size_t)(r0 + 8) * 512 + col]) = o1;
        }
    }
}

// =====================================================================
extern "C" void kernel_launch(void* const* d_in, const int* in_sizes, int n_in,
                              void* d_out, int out_size)
{
    const float* x   = (const float*)d_in[0];
    const float* wi  = (const float*)d_in[1];
    const float* bi  = (const float*)d_in[2];
    const float* wo  = (const float*)d_in[3];
    const float* bo  = (const float*)d_in[4];
    const float* rpe = (const float*)d_in[5];
    float* out = (float*)d_out;

    static bool attr_done = false;
    if (!attr_done) {
        cudaFuncSetAttribute(qkv_gemm_mma,
            cudaFuncAttributeMaxDynamicSharedMemorySize, GSMEMB);
        cudaFuncSetAttribute(out_gemm_mma,
            cudaFuncAttributeMaxDynamicSharedMemorySize, GSMEMB);
        cudaFuncSetAttribute(attn_mma,
            cudaFuncAttributeMaxDynamicSharedMemorySize, AT_SMEMB);
        attr_done = true;
    }

    const int mtiles = M_IMG / 128;   // 1024

    cvt_all<<<4096, 256>>>(x, wi, wo, bi);
    qkv_gemm_mma<<<dim3(1536 / 128, mtiles), 128, GSMEMB>>>(bi);
    attn_mma<<<dim3(NB, NHEADS), 64, AT_SMEMB>>>(rpe);
    out_gemm_mma<<<dim3(512 / 128, mtiles), 128, GSMEMB>>>(bo, out);
}

// round 9
// speedup vs baseline: 4.8443x; 1.4047x over previous
#include <cuda_runtime.h>
#include <cuda_fp16.h>
#include <cstdint>

// ---------------- problem constants ----------------
#define M_IMG   131072      // 8 * 128 * 128 image pixels
#define NB      2888        // 8 * 19 * 19 windows
#define QHW     19
#define NHEADS  16

// ---------------- scratch (static device allocations) ----------------
__device__ __align__(16) __half g_xh[67108864];    // x fp16 (image layout)
__device__ __align__(16) __half g_wi_h[786432];    // W_in  fp16
__device__ __align__(16) __half g_wo_h[262144];    // W_out fp16
__device__ __align__(16) __half g_qkvh[201326592]; // qkv fp16 (image layout)
__device__ __align__(16) __half g_atth[67108864];  // attn out fp16 (image layout)
__device__ __align__(16) __half g_hrow[1536];      // halo qkv row = fp16(bias)

__device__ __forceinline__ void ldsm4(unsigned& r0, unsigned& r1, unsigned& r2, unsigned& r3,
                                      uint32_t addr) {
    asm volatile("ldmatrix.sync.aligned.m8n8.x4.shared.b16 {%0,%1,%2,%3}, [%4];"
                 : "=r"(r0), "=r"(r1), "=r"(r2), "=r"(r3) : "r"(addr));
}

__device__ __forceinline__ void mma_f16(float& d0, float& d1, float& d2, float& d3,
                                        unsigned a0, unsigned a1, unsigned a2, unsigned a3,
                                        unsigned b0, unsigned b1) {
    asm volatile("mma.sync.aligned.m16n8k16.row.col.f32.f16.f16.f32 "
                 "{%0,%1,%2,%3}, {%4,%5,%6,%7}, {%8,%9}, {%0,%1,%2,%3};"
                 : "+f"(d0), "+f"(d1), "+f"(d2), "+f"(d3)
                 : "r"(a0), "r"(a1), "r"(a2), "r"(a3), "r"(b0), "r"(b1));
}

__device__ __forceinline__ void cp16(uint32_t dst, const void* src) {
    asm volatile("cp.async.cg.shared.global [%0], [%1], 16;" :: "r"(dst), "l"(src));
}
__device__ __forceinline__ void cp_commit() { asm volatile("cp.async.commit_group;"); }
template <int N>
__device__ __forceinline__ void cp_waitg() {
    asm volatile("cp.async.wait_group %0;" :: "n"(N) : "memory");
}

// GEMM smem: rows of 32 halfs (64B data) padded to 80B; A=128 rows, B=128 rows
#define ROWB   80
#define ATILEB (128 * ROWB)              // 10240
#define STAGEB (2 * ATILEB)              // 20480
#define NSTAGE 3
#define GSMEMB (NSTAGE * STAGEB)         // 61440

// one stage (BK=32 halfs = 2 k16-steps), warp tile 64x64
__device__ __forceinline__ void compute_stage64h(uint32_t aB, uint32_t bB,
                                                 float acc[4][8][4]) {
    #pragma unroll
    for (int kk = 0; kk < 2; kk++) {
        unsigned af[4][4];
        #pragma unroll
        for (int mi = 0; mi < 4; mi++)
            ldsm4(af[mi][0], af[mi][1], af[mi][2], af[mi][3],
                  aB + (unsigned)(mi * 16 * ROWB + kk * 32));
        unsigned bf[4][4];
        #pragma unroll
        for (int p = 0; p < 4; p++)
            ldsm4(bf[p][0], bf[p][1], bf[p][2], bf[p][3],
                  bB + (unsigned)(p * 16 * ROWB + kk * 32));
        #pragma unroll
        for (int mi = 0; mi < 4; mi++)
            #pragma unroll
            for (int p = 0; p < 4; p++) {
                mma_f16(acc[mi][2*p][0], acc[mi][2*p][1], acc[mi][2*p][2], acc[mi][2*p][3],
                        af[mi][0], af[mi][1], af[mi][2], af[mi][3],
                        bf[p][0], bf[p][2]);
                mma_f16(acc[mi][2*p+1][0], acc[mi][2*p+1][1], acc[mi][2*p+1][2], acc[mi][2*p+1][3],
                        af[mi][0], af[mi][1], af[mi][2], af[mi][3],
                        bf[p][1], bf[p][3]);
            }
    }
}

// ---------------- fp16 preconvert ----------------
#define XN4  16777216
#define WIN4 196608
#define WON4 65536
__global__ void cvt_all(const float* __restrict__ x, const float* __restrict__ wi,
                        const float* __restrict__ wo, const float* __restrict__ bi) {
    if (blockIdx.x == 0) {
        for (int i = threadIdx.x; i < 1536; i += 256)
            g_hrow[i] = __float2half_rn(bi[i]);
    }
    const int stride = gridDim.x * blockDim.x;
    for (int i = blockIdx.x * blockDim.x + threadIdx.x;
         i < XN4 + WIN4 + WON4; i += stride) {
        const float4* src;
        uint2* dst;
        if (i < XN4) {
            src = reinterpret_cast<const float4*>(x) + i;
            dst = reinterpret_cast<uint2*>(g_xh) + i;
        } else if (i < XN4 + WIN4) {
            src = reinterpret_cast<const float4*>(wi) + (i - XN4);
            dst = reinterpret_cast<uint2*>(g_wi_h) + (i - XN4);
        } else {
            src = reinterpret_cast<const float4*>(wo) + (i - XN4 - WIN4);
            dst = reinterpret_cast<uint2*>(g_wo_h) + (i - XN4 - WIN4);
        }
        float4 v = *src;
        __half2 h0 = __floats2half2_rn(v.x, v.y);
        __half2 h1 = __floats2half2_rn(v.z, v.w);
        uint2 u;
        u.x = reinterpret_cast<unsigned&>(h0);
        u.y = reinterpret_cast<unsigned&>(h1);
        *dst = u;
    }
}

// =====================================================================
// GEMM 1 (fp16, 64x64 warp tiles): qkv = x_h @ Win^T + bin -> fp16
// =====================================================================
__global__ __launch_bounds__(128, 2) void qkv_gemm_mma(const float* __restrict__ bias)
{
    extern __shared__ char smem[];
    const int tid = threadIdx.x, lane = tid & 31, wid = tid >> 5;
    const int wm = wid >> 1, wn = wid & 1;
    const int m0 = blockIdx.y * 128, n0 = blockIdx.x * 128;

    const int lrow = tid >> 2;       // 0..31
    const int seg  = tid & 3;        // 16B segment (8 halfs)

    const __half* asrc = g_xh  + (size_t)(m0 + lrow) * 512 + seg * 8;
    const __half* bsrc = g_wi_h + (size_t)(n0 + lrow) * 512 + seg * 8;

    const uint32_t s0 = (uint32_t)__cvta_generic_to_shared(smem);
    const uint32_t adst = s0 + lrow * ROWB + seg * 16;
    const uint32_t bdst = adst + ATILEB;

    const uint32_t foff = (uint32_t)((lane & 15) * ROWB + (lane >> 4) * 16);
    const uint32_t aoff = wm * 64 * ROWB + foff;
    const uint32_t boff = wn * 64 * ROWB + foff;

    float acc[4][8][4];
    #pragma unroll
    for (int i = 0; i < 4; i++)
        #pragma unroll
        for (int j = 0; j < 8; j++)
            #pragma unroll
            for (int q = 0; q < 4; q++) acc[i][j][q] = 0.f;

    auto load = [&](int it, int buf) {
        const int k0 = it * 32;
        const uint32_t off = buf * STAGEB;
        #pragma unroll
        for (int i = 0; i < 4; i++)
            cp16(adst + off + i * 32 * ROWB, asrc + k0 + (size_t)i * 32 * 512);
        #pragma unroll
        for (int i = 0; i < 4; i++)
            cp16(bdst + off + i * 32 * ROWB, bsrc + k0 + (size_t)i * 32 * 512);
        cp_commit();
    };

    load(0, 0);
    load(1, 1);

    #pragma unroll 1
    for (int it = 0; it < 16; ++it) {
        if (it < 15) cp_waitg<1>(); else cp_waitg<0>();
        __syncthreads();
        if (it + 2 < 16) load(it + 2, (it + 2) % NSTAGE);
        const int cur = it % NSTAGE;
        compute_stage64h(s0 + cur * STAGEB + aoff,
                         s0 + cur * STAGEB + ATILEB + boff, acc);
    }

    #pragma unroll
    for (int i = 0; i < 4; i++) {
        const int r0 = m0 + wm * 64 + i * 16 + (lane >> 2);
        #pragma unroll
        for (int j = 0; j < 8; j++) {
            const int col = n0 + wn * 64 + j * 8 + (lane & 3) * 2;
            const float b0 = bias[col], b1 = bias[col + 1];
            __half2 o0 = __floats2half2_rn(acc[i][j][0] + b0, acc[i][j][1] + b1);
            __half2 o1 = __floats2half2_rn(acc[i][j][2] + b0, acc[i][j][3] + b1);
            *reinterpret_cast<__half2*>(&g_qkvh[(size_t)r0 * 1536 + col]) = o0;
            *reinterpret_cast<__half2*>(&g_qkvh[(size_t)(r0 + 8) * 1536 + col]) = o1;
        }
    }
}

// =====================================================================
// Attention (fp16 mma): one block per (window, head), 64 threads.
// =====================================================================
// byte offsets inside dynamic smem
#define AT_QS   0                        // [64][40h] = 5120
#define AT_KS   5120                     // [64][40h] = 5120
#define AT_VT   10240                    // [32][72h] = 4608
#define AT_PH   14848                    // [64][72h] = 9216
#define AT_SP   24064                    // [64][68f] = 17408
#define AT_BSM  41472                    // [169f]    = 676
#define AT_PIX  42148                    // [49i]     = 196
#define AT_SMEMB 42368

__global__ __launch_bounds__(64) void attn_mma(const float* __restrict__ rpe)
{
    extern __shared__ char sm[];
    __half* qs  = reinterpret_cast<__half*>(sm + AT_QS);
    __half* ks  = reinterpret_cast<__half*>(sm + AT_KS);
    __half* vT  = reinterpret_cast<__half*>(sm + AT_VT);
    __half* Ph  = reinterpret_cast<__half*>(sm + AT_PH);
    float*  SP  = reinterpret_cast<float*>(sm + AT_SP);
    float*  bsm = reinterpret_cast<float*>(sm + AT_BSM);
    int*  s_pix = reinterpret_cast<int*>(sm + AT_PIX);

    const int tid  = threadIdx.x;
    const int wh   = tid >> 5;
    const int lane = tid & 31;

    const int wb   = blockIdx.x;
    const int head = blockIdx.y;
    const float scale = 0.17677669529663687f;   // 32^-0.5

    if (tid < 49) {
        const int b  = wb / (QHW * QHW);
        const int rm = wb - b * (QHW * QHW);
        const int qi = rm / QHW, qj = rm - (rm / QHW) * QHW;
        const int r = qi * 7 + tid / 7 - 2;
        const int c = qj * 7 + (tid % 7) - 2;
        s_pix[tid] = ((unsigned)r < 128u && (unsigned)c < 128u)
                   ? (b * 16384 + r * 128 + c) : -1;
    }
    __syncthreads();

    // zero vT (token cols 49-63 must be exactly 0 for P@V)
    #pragma unroll 1
    for (int i = tid; i < 32 * 72 / 2; i += 64)
        reinterpret_cast<unsigned*>(vT)[i] = 0u;

    // gather q/k rows + transpose v
    #pragma unroll 1
    for (int i = tid; i < 196; i += 64) {          // 49 tokens * 4 chunks of 8 halfs
        const int t = i >> 2, d8 = (i & 3) * 8;
        const int pix = s_pix[t];
        const __half* p = ((pix >= 0) ? g_qkvh + (size_t)pix * 1536 : g_hrow)
                        + head * 32 + d8;
        uint4 q4 = *reinterpret_cast<const uint4*>(p);
        uint4 k4 = *reinterpret_cast<const uint4*>(p + 512);
        uint4 v4 = *reinterpret_cast<const uint4*>(p + 1024);
        *reinterpret_cast<uint4*>(&qs[t * 40 + d8]) = q4;
        *reinterpret_cast<uint4*>(&ks[t * 40 + d8]) = k4;
        const __half2* vp = reinterpret_cast<const __half2*>(&v4);
        #pragma unroll
        for (int j = 0; j < 4; j++) {
            __half2 hv = vp[j];
            vT[(d8 + 2 * j) * 72 + t]     = __low2half(hv);
            vT[(d8 + 2 * j + 1) * 72 + t] = __high2half(hv);
        }
    }
    for (int i = tid; i < 169; i += 64) bsm[i] = rpe[i * NHEADS + head];
    __syncthreads();

    const int mrow = lane >> 2;
    const int c2 = (lane & 3) * 2;
    const uint32_t fo40 = (uint32_t)((lane & 15) * ROWB + (lane >> 4) * 16);
    const uint32_t fo72 = (uint32_t)((lane & 15) * 144 + (lane >> 4) * 16);

    // ---- QK^T: warp wh computes S cols [wh*32, wh*32+32) ----
    {
        const uint32_t qb = (uint32_t)__cvta_generic_to_shared(qs) + fo40;
        const uint32_t kb = (uint32_t)__cvta_generic_to_shared(ks) + wh * 32 * ROWB + fo40;

        float acc[4][4][4];
        #pragma unroll
        for (int i = 0; i < 4; i++)
            #pragma unroll
            for (int j = 0; j < 4; j++)
                #pragma unroll
                for (int q = 0; q < 4; q++) acc[i][j][q] = 0.f;

        #pragma unroll
        for (int kk = 0; kk < 2; kk++) {
            unsigned af[4][4];
            #pragma unroll
            for (int mi = 0; mi < 4; mi++)
                ldsm4(af[mi][0], af[mi][1], af[mi][2], af[mi][3],
                      qb + (unsigned)(mi * 16 * ROWB + kk * 32));
            unsigned bf[2][4];
            #pragma unroll
            for (int p = 0; p < 2; p++)
                ldsm4(bf[p][0], bf[p][1], bf[p][2], bf[p][3],
                      kb + (unsigned)(p * 16 * ROWB + kk * 32));
            #pragma unroll
            for (int mi = 0; mi < 4; mi++)
                #pragma unroll
                for (int p = 0; p < 2; p++) {
                    mma_f16(acc[mi][2*p][0], acc[mi][2*p][1], acc[mi][2*p][2], acc[mi][2*p][3],
                            af[mi][0], af[mi][1], af[mi][2], af[mi][3],
                            bf[p][0], bf[p][2]);
                    mma_f16(acc[mi][2*p+1][0], acc[mi][2*p+1][1], acc[mi][2*p+1][2], acc[mi][2*p+1][3],
                            af[mi][0], af[mi][1], af[mi][2], af[mi][3],
                            bf[p][1], bf[p][3]);
                }
        }

        #pragma unroll
        for (int mi = 0; mi < 4; mi++)
            #pragma unroll
            for (int nj = 0; nj < 4; nj++) {
                const int colb = wh * 32 + nj * 8 + c2;
                *reinterpret_cast<float2*>(&SP[(mi * 16 + mrow) * 68 + colb]) =
                    make_float2(acc[mi][nj][0], acc[mi][nj][1]);
                *reinterpret_cast<float2*>(&SP[(mi * 16 + mrow + 8) * 68 + colb]) =
                    make_float2(acc[mi][nj][2], acc[mi][nj][3]);
            }
    }
    __syncthreads();

    // ---- softmax over 49 valid cols; write P rows as fp16 ----
    if (tid < 49) {
        const int l = tid;
        float* row = SP + l * 68;
        const int lr = l / 7, lc = l - lr * 7;
        float s[49];
        float mx = -1e30f;
        #pragma unroll
        for (int m2 = 0; m2 < 49; m2++) {
            const int mr = m2 / 7, mc = m2 - mr * 7;
            const float v = row[m2] * scale + bsm[(lr - mr + 6) * 13 + (lc - mc + 6)];
            s[m2] = v;
            mx = fmaxf(mx, v);
        }
        float sum = 0.f;
        #pragma unroll
        for (int m2 = 0; m2 < 49; m2++) {
            const float e = __expf(s[m2] - mx);
            s[m2] = e;
            sum += e;
        }
        const float inv = 1.f / sum;
        __half* prow = Ph + l * 72;
        #pragma unroll
        for (int m2 = 0; m2 < 49; m2++) prow[m2] = __float2half_rn(s[m2] * inv);
        #pragma unroll
        for (int m2 = 49; m2 < 64; m2++) prow[m2] = __ushort_as_half(0);
    }
    __syncthreads();

    // ---- P @ V: warp wh computes O cols [wh*16, wh*16+16) ----
    {
        const uint32_t pb = (uint32_t)__cvta_generic_to_shared(Ph) + fo72;
        const uint32_t vb = (uint32_t)__cvta_generic_to_shared(vT) + wh * 16 * 144 + fo72;

        float o[4][2][4];
        #pragma unroll
        for (int i = 0; i < 4; i++)
            #pragma unroll
            for (int j = 0; j < 2; j++)
                #pragma unroll
                for (int q = 0; q < 4; q++) o[i][j][q] = 0.f;

        #pragma unroll
        for (int kk = 0; kk < 4; kk++) {
            unsigned af[4][4];
            #pragma unroll
            for (int mi = 0; mi < 4; mi++)
                ldsm4(af[mi][0], af[mi][1], af[mi][2], af[mi][3],
                      pb + (unsigned)(mi * 16 * 144 + kk * 32));
            unsigned bf[4];
            ldsm4(bf[0], bf[1], bf[2], bf[3], vb + (unsigned)(kk * 32));
            #pragma unroll
            for (int mi = 0; mi < 4; mi++) {
                mma_f16(o[mi][0][0], o[mi][0][1], o[mi][0][2], o[mi][0][3],
                        af[mi][0], af[mi][1], af[mi][2], af[mi][3], bf[0], bf[2]);
                mma_f16(o[mi][1][0], o[mi][1][1], o[mi][1][2], o[mi][1][3],
                        af[mi][0], af[mi][1], af[mi][2], af[mi][3], bf[1], bf[3]);
            }
        }

        #pragma unroll
        for (int mi = 0; mi < 4; mi++) {
            const int m = mi * 16 + mrow;
            const int pix0 = (m < 49) ? s_pix[m] : -1;
            const int pix1 = (m + 8 < 49) ? s_pix[m + 8] : -1;
            #pragma unroll
            for (int nj = 0; nj < 2; nj++) {
                const int col = head * 32 + wh * 16 + nj * 8 + c2;
                if (pix0 >= 0) {
                    __half2 u = __floats2half2_rn(o[mi][nj][0], o[mi][nj][1]);
                    *reinterpret_cast<__half2*>(&g_atth[(size_t)pix0 * 512 + col]) = u;
                }
                if (pix1 >= 0) {
                    __half2 u = __floats2half2_rn(o[mi][nj][2], o[mi][nj][3]);
                    *reinterpret_cast<__half2*>(&g_atth[(size_t)pix1 * 512 + col]) = u;
                }
            }
        }
    }
}

// =====================================================================
// GEMM 2 (fp16, 64x64 warp tiles): out = att_h @ Wout^T + bout (direct)
// =====================================================================
__global__ __launch_bounds__(128, 2) void out_gemm_mma(
    const float* __restrict__ bias, float* __restrict__ out)
{
    extern __shared__ char smem[];
    const int tid = threadIdx.x, lane = tid & 31, wid = tid >> 5;
    const int wm = wid >> 1, wn = wid & 1;
    const int m0 = blockIdx.y * 128, n0 = blockIdx.x * 128;

    const int lrow = tid >> 2;
    const int seg  = tid & 3;

    const __half* asrc = g_atth + (size_t)(m0 + lrow) * 512 + seg * 8;
    const __half* bsrc = g_wo_h + (size_t)(n0 + lrow) * 512 + seg * 8;

    const uint32_t s0 = (uint32_t)__cvta_generic_to_shared(smem);
    const uint32_t adst = s0 + lrow * ROWB + seg * 16;
    const uint32_t bdst = adst + ATILEB;

    const uint32_t foff = (uint32_t)((lane & 15) * ROWB + (lane >> 4) * 16);
    const uint32_t aoff = wm * 64 * ROWB + foff;
    const uint32_t boff = wn * 64 * ROWB + foff;

    float acc[4][8][4];
    #pragma unroll
    for (int i = 0; i < 4; i++)
        #pragma unroll
        for (int j = 0; j < 8; j++)
            #pragma unroll
            for (int q = 0; q < 4; q++) acc[i][j][q] = 0.f;

    auto load = [&](int it, int buf) {
        const int k0 = it * 32;
        const uint32_t off = buf * STAGEB;
        #pragma unroll
        for (int i = 0; i < 4; i++)
            cp16(adst + off + i * 32 * ROWB, asrc + k0 + (size_t)i * 32 * 512);
        #pragma unroll
        for (int i = 0; i < 4; i++)
            cp16(bdst + off + i * 32 * ROWB, bsrc + k0 + (size_t)i * 32 * 512);
        cp_commit();
    };

    load(0, 0);
    load(1, 1);

    #pragma unroll 1
    for (int it = 0; it < 16; ++it) {
        if (it < 15) cp_waitg<1>(); else cp_waitg<0>();
        __syncthreads();
        if (it + 2 < 16) load(it + 2, (it + 2) % NSTAGE);
        const int cur = it % NSTAGE;
        compute_stage64h(s0 + cur * STAGEB + aoff,
                         s0 + cur * STAGEB + ATILEB + boff, acc);
    }

    #pragma unroll
    for (int i = 0; i < 4; i++) {
        const int r0 = m0 + wm * 64 + i * 16 + (lane >> 2);
        #pragma unroll
        for (int j = 0; j < 8; j++) {
            const int col = n0 + wn * 64 + j * 8 + (lane & 3) * 2;
            const float b0 = bias[col], b1 = bias[col + 1];
            float2 o0 = make_float2(acc[i][j][0] + b0, acc[i][j][1] + b1);
            float2 o1 = make_float2(acc[i][j][2] + b0, acc[i][j][3] + b1);
            *reinterpret_cast<float2*>(&out[(size_t)r0 * 512 + col]) = o0;
            *reinterpret_cast<float2*>(&out[(size_t)(r0 + 8) * 512 + col]) = o1;
        }
    }
}

// =====================================================================
extern "C" void kernel_launch(void* const* d_in, const int* in_sizes, int n_in,
                              void* d_out, int out_size)
{
    const float* x   = (const float*)d_in[0];
    const float* wi  = (const float*)d_in[1];
    const float* bi  = (const float*)d_in[2];
    const float* wo  = (const float*)d_in[3];
    const float* bo  = (const float*)d_in[4];
    const float* rpe = (const float*)d_in[5];
    float* out = (float*)d_out;

    static bool attr_done = false;
    if (!attr_done) {
        cudaFuncSetAttribute(qkv_gemm_mma,
            cudaFuncAttributeMaxDynamicSharedMemorySize, GSMEMB);
        cudaFuncSetAttribute(out_gemm_mma,
            cudaFuncAttributeMaxDynamicSharedMemorySize, GSMEMB);
        cudaFuncSetAttribute(attn_mma,
            cudaFuncAttributeMaxDynamicSharedMemorySize, AT_SMEMB);
        attr_done = true;
    }

    const int mtiles = M_IMG / 128;   // 1024

    cvt_all<<<4096, 256>>>(x, wi, wo, bi);
    qkv_gemm_mma<<<dim3(1536 / 128, mtiles), 128, GSMEMB>>>(bi);
    attn_mma<<<dim3(NB, NHEADS), 64, AT_SMEMB>>>(rpe);
    out_gemm_mma<<<dim3(512 / 128, mtiles), 128, GSMEMB>>>(bo, out);
}